// round 8
// baseline (speedup 1.0000x reference)
#include <cuda_runtime.h>

// Fused DGM network, R7.
// Config: 128 threads/CTA, TM=64 rows, per-thread 8 rows x 8 cols.
// Rationale (R6 ncu): L1 return BW is charged per-lane bytes; R6 moved
// 2.5 B/MAC. This config moves (32B W + 32B A)/64 MACs = 1.0 B/MAC and
// balances the FMA pipe (32 FFMA2 = 64 SMSP-cyc vs 16 L1-cyc/warp-k).
// S/SR/XT tiles transposed [k][row] in SMEM; u-projections in SMEM;
// H kept packed in registers across the G-GEMM; 3 syncs/layer.

namespace {
constexpr int XDIM   = 100;
constexpr int XTDIM  = 101;
constexpr int HIDDEN = 128;
constexpr int TM     = 64;    // rows per CTA
constexpr int NTHR   = 128;   // 4 warps

// smem layout (bytes)
constexpr int OFF_U   = 0;                        // 4 planes*32 slots*128 thr ull
constexpr int OFF_A   = OFF_U + 4 * 32 * NTHR * 8;   // 131072
constexpr int OFF_B   = OFF_A + HIDDEN * TM * 4;     // +32768 = 163840
constexpr int OFF_XT  = OFF_B + HIDDEN * TM * 4;     // +32768 = 196608
constexpr int SMEM_TOTAL = OFF_XT + XTDIM * TM * 4;  // +25856 = 222464
}

using ull = unsigned long long;

__device__ __forceinline__ ull pack2(float lo, float hi) {
    ull r;
    asm("mov.b64 %0, {%1, %2};" : "=l"(r) : "f"(lo), "f"(hi));
    return r;
}
__device__ __forceinline__ void unpack2(ull v, float& lo, float& hi) {
    asm("mov.b64 {%0, %1}, %2;" : "=f"(lo), "=f"(hi) : "l"(v));
}
__device__ __forceinline__ void fma2(ull& d, ull a, ull b) {
    asm("fma.rn.f32x2 %0, %1, %2, %0;" : "+l"(d) : "l"(a), "l"(b));
}
__device__ __forceinline__ ull add2(ull a, ull b) {
    ull d;
    asm("add.rn.f32x2 %0, %1, %2;" : "=l"(d) : "l"(a), "l"(b));
    return d;
}

// tanh via exp: ~1e-7 abs error, saturates correctly at +/-inf.
__device__ __forceinline__ float fast_tanh(float v) {
    float e = __expf(2.0f * v);
    return 1.0f - __fdividef(2.0f, e + 1.0f);
}

// acc[8][4] (f32x2 col-pairs) = bias[c0..c0+8) +
//     A[r0..r0+8)[0..K) @ W[0..K)[c0..c0+8)
// A transposed in shared: sAT[k*64 + row]; rows r0..r0+7 via 2x LDS.128.
// W row-major [K][128] in global. Manual 1-deep register double buffer.
template <int K>
__device__ __forceinline__ void gemmT8x8(const float* __restrict__ sAT, int r0,
                                         const float* __restrict__ W,
                                         const float* __restrict__ bias, int c0,
                                         ull acc[8][4]) {
    const ulonglong2* b2 = reinterpret_cast<const ulonglong2*>(bias + c0);
    ulonglong2 bb0 = b2[0];
    ulonglong2 bb1 = b2[1];
#pragma unroll
    for (int ri = 0; ri < 8; ++ri) {
        acc[ri][0] = bb0.x; acc[ri][1] = bb0.y;
        acc[ri][2] = bb1.x; acc[ri][3] = bb1.y;
    }

    const float4* a0p = reinterpret_cast<const float4*>(sAT + r0);      // +k*16
    const float4* a1p = reinterpret_cast<const float4*>(sAT + r0 + 4);  // +k*16
    const char* wbase = reinterpret_cast<const char*>(W + c0);

    float4 a0 = a0p[0];
    float4 a1 = a1p[0];
    ulonglong2 w0 = reinterpret_cast<const ulonglong2*>(wbase)[0];
    ulonglong2 w1 = reinterpret_cast<const ulonglong2*>(wbase)[1];

#pragma unroll 2
    for (int k = 0; k < K; ++k) {
        float4 na0, na1;
        ulonglong2 nw0, nw1;
        if (k + 1 < K) {
            na0 = a0p[(k + 1) * 16];
            na1 = a1p[(k + 1) * 16];
            const ulonglong2* wp = reinterpret_cast<const ulonglong2*>(
                wbase + (size_t)(k + 1) * (HIDDEN * 4));
            nw0 = wp[0];
            nw1 = wp[1];
        }
        ull av;
        av = pack2(a0.x, a0.x);
        fma2(acc[0][0], av, w0.x); fma2(acc[0][1], av, w0.y);
        fma2(acc[0][2], av, w1.x); fma2(acc[0][3], av, w1.y);
        av = pack2(a0.y, a0.y);
        fma2(acc[1][0], av, w0.x); fma2(acc[1][1], av, w0.y);
        fma2(acc[1][2], av, w1.x); fma2(acc[1][3], av, w1.y);
        av = pack2(a0.z, a0.z);
        fma2(acc[2][0], av, w0.x); fma2(acc[2][1], av, w0.y);
        fma2(acc[2][2], av, w1.x); fma2(acc[2][3], av, w1.y);
        av = pack2(a0.w, a0.w);
        fma2(acc[3][0], av, w0.x); fma2(acc[3][1], av, w0.y);
        fma2(acc[3][2], av, w1.x); fma2(acc[3][3], av, w1.y);
        av = pack2(a1.x, a1.x);
        fma2(acc[4][0], av, w0.x); fma2(acc[4][1], av, w0.y);
        fma2(acc[4][2], av, w1.x); fma2(acc[4][3], av, w1.y);
        av = pack2(a1.y, a1.y);
        fma2(acc[5][0], av, w0.x); fma2(acc[5][1], av, w0.y);
        fma2(acc[5][2], av, w1.x); fma2(acc[5][3], av, w1.y);
        av = pack2(a1.z, a1.z);
        fma2(acc[6][0], av, w0.x); fma2(acc[6][1], av, w0.y);
        fma2(acc[6][2], av, w1.x); fma2(acc[6][3], av, w1.y);
        av = pack2(a1.w, a1.w);
        fma2(acc[7][0], av, w0.x); fma2(acc[7][1], av, w0.y);
        fma2(acc[7][2], av, w1.x); fma2(acc[7][3], av, w1.y);

        a0 = na0; a1 = na1; w0 = nw0; w1 = nw1;
    }
}

__global__ void __launch_bounds__(NTHR, 1) dgm_fused_kernel(
    const float* __restrict__ x, const float* __restrict__ t,
    const float* __restrict__ Sw_w, const float* __restrict__ Sw_b,
    const float* __restrict__ Uz_w, const float* __restrict__ Uz_b,
    const float* __restrict__ Wsz_w, const float* __restrict__ Wsz_b,
    const float* __restrict__ Ug_w, const float* __restrict__ Ug_b,
    const float* __restrict__ Wsg_w, const float* __restrict__ Wsg_b,
    const float* __restrict__ Ur_w, const float* __restrict__ Ur_b,
    const float* __restrict__ Wsr_w, const float* __restrict__ Wsr_b,
    const float* __restrict__ Uh_w, const float* __restrict__ Uh_b,
    const float* __restrict__ Wsh_w, const float* __restrict__ Wsh_b,
    const float* __restrict__ Wf_w, const float* __restrict__ Wf_b,
    const int* __restrict__ n_layers_p, float* __restrict__ out) {
    extern __shared__ char smem[];
    ull*   uS   = reinterpret_cast<ull*>(smem + OFF_U);
    float* bufA = reinterpret_cast<float*>(smem + OFF_A);   // [128][64]
    float* bufB = reinterpret_cast<float*>(smem + OFF_B);   // [128][64]
    float* sXT  = reinterpret_cast<float*>(smem + OFF_XT);  // [101][64]

    const int tid = threadIdx.x;
    const int row0_g = blockIdx.x * TM;

    // ---- stage xt (transposed): sXT[k*64 + m] = xt[m][k] ----
    {
        const float4* x4 = reinterpret_cast<const float4*>(x);  // row = 25 float4
        for (int idx = tid; idx < TM * 25; idx += NTHR) {
            int m = idx / 25;
            int q = idx - m * 25;
            float4 v = x4[(size_t)(row0_g + m) * 25 + q];
            sXT[(q * 4 + 0) * 64 + m] = v.x;
            sXT[(q * 4 + 1) * 64 + m] = v.y;
            sXT[(q * 4 + 2) * 64 + m] = v.z;
            sXT[(q * 4 + 3) * 64 + m] = v.w;
        }
        if (tid < TM) sXT[100 * 64 + tid] = t[row0_g + tid];
    }
    __syncthreads();

    // Mapping: warp w owns rows [16w, 16w+16); lanes split 2 row-octs x 16
    // col-chunks: r0 = 16w + (lane>>4)*8, c0 = (lane&15)*8.
    const int warp = tid >> 5;
    const int lane = tid & 31;
    const int r0 = warp * 16 + (lane >> 4) * 8;  // 0..56, mult of 8
    const int c0 = (lane & 15) * 8;              // 0..120

    ull acc[8][4];

    // ---- phase 1: S1 = tanh(xt@Sw + b) -> bufA ----
    gemmT8x8<XTDIM>(sXT, r0, Sw_w, Sw_b, c0, acc);
    {
        float v[8][8];
#pragma unroll
        for (int ri = 0; ri < 8; ++ri)
#pragma unroll
            for (int j = 0; j < 4; ++j) {
                float lo, hi;
                unpack2(acc[ri][j], lo, hi);
                v[ri][2 * j]     = fast_tanh(lo);
                v[ri][2 * j + 1] = fast_tanh(hi);
            }
#pragma unroll
        for (int c = 0; c < 8; ++c) {
            *reinterpret_cast<float4*>(bufA + (c0 + c) * 64 + r0) =
                make_float4(v[0][c], v[1][c], v[2][c], v[3][c]);
            *reinterpret_cast<float4*>(bufA + (c0 + c) * 64 + r0 + 4) =
                make_float4(v[4][c], v[5][c], v[6][c], v[7][c]);
        }
    }
    // ---- u-projections (raw, pre-activation) -> uS ----
    // uS layout: [plane p][slot s = ri*4+j][tid]
    gemmT8x8<XTDIM>(sXT, r0, Uz_w, Uz_b, c0, acc);
#pragma unroll
    for (int ri = 0; ri < 8; ++ri)
#pragma unroll
        for (int j = 0; j < 4; ++j)
            uS[(0 * 32 + ri * 4 + j) * NTHR + tid] = acc[ri][j];
    gemmT8x8<XTDIM>(sXT, r0, Ug_w, Ug_b, c0, acc);
#pragma unroll
    for (int ri = 0; ri < 8; ++ri)
#pragma unroll
        for (int j = 0; j < 4; ++j)
            uS[(1 * 32 + ri * 4 + j) * NTHR + tid] = acc[ri][j];
    gemmT8x8<XTDIM>(sXT, r0, Ur_w, Ur_b, c0, acc);
#pragma unroll
    for (int ri = 0; ri < 8; ++ri)
#pragma unroll
        for (int j = 0; j < 4; ++j)
            uS[(2 * 32 + ri * 4 + j) * NTHR + tid] = acc[ri][j];
    gemmT8x8<XTDIM>(sXT, r0, Uh_w, Uh_b, c0, acc);
#pragma unroll
    for (int ri = 0; ri < 8; ++ri)
#pragma unroll
        for (int j = 0; j < 4; ++j)
            uS[(3 * 32 + ri * 4 + j) * NTHR + tid] = acc[ri][j];
    __syncthreads();

    const int nl = *n_layers_p;
    float* cur = bufA;
    float* nxt = bufB;

#pragma unroll 1
    for (int l = 1; l < nl; ++l) {
        // ---- R = tanh(ur + S@Wsr); nxt = S * R ----
        gemmT8x8<HIDDEN>(cur, r0, Wsr_w, Wsr_b, c0, acc);
#pragma unroll
        for (int ri = 0; ri < 8; ++ri)
#pragma unroll
            for (int j = 0; j < 4; ++j)
                acc[ri][j] = add2(acc[ri][j], uS[(2 * 32 + ri * 4 + j) * NTHR + tid]);
        {
            float v[8][8];
#pragma unroll
            for (int ri = 0; ri < 8; ++ri)
#pragma unroll
                for (int j = 0; j < 4; ++j) {
                    float lo, hi;
                    unpack2(acc[ri][j], lo, hi);
                    v[ri][2 * j]     = fast_tanh(lo);
                    v[ri][2 * j + 1] = fast_tanh(hi);
                }
#pragma unroll
            for (int c = 0; c < 8; ++c) {
                float4 s_lo = *reinterpret_cast<const float4*>(cur + (c0 + c) * 64 + r0);
                float4 s_hi = *reinterpret_cast<const float4*>(cur + (c0 + c) * 64 + r0 + 4);
                *reinterpret_cast<float4*>(nxt + (c0 + c) * 64 + r0) =
                    make_float4(s_lo.x * v[0][c], s_lo.y * v[1][c],
                                s_lo.z * v[2][c], s_lo.w * v[3][c]);
                *reinterpret_cast<float4*>(nxt + (c0 + c) * 64 + r0 + 4) =
                    make_float4(s_hi.x * v[4][c], s_hi.y * v[5][c],
                                s_hi.z * v[6][c], s_hi.w * v[7][c]);
            }
        }
        __syncthreads();  // nxt = S*R complete

        // ---- H = uh + SR@Wsh + bh  (kept packed in registers) ----
        ull H[8][4];
        gemmT8x8<HIDDEN>(nxt, r0, Wsh_w, Wsh_b, c0, acc);
#pragma unroll
        for (int ri = 0; ri < 8; ++ri)
#pragma unroll
            for (int j = 0; j < 4; ++j)
                H[ri][j] = add2(acc[ri][j], uS[(3 * 32 + ri * 4 + j) * NTHR + tid]);
        __syncthreads();  // all warps done reading nxt (SR); nxt reusable

        // ---- Z = tanh(uz + S@Wsz); nxt = Z * S (own slots) ----
        gemmT8x8<HIDDEN>(cur, r0, Wsz_w, Wsz_b, c0, acc);
        {
            float v[8][8];
#pragma unroll
            for (int ri = 0; ri < 8; ++ri)
#pragma unroll
                for (int j = 0; j < 4; ++j) {
                    float lo, hi;
                    unpack2(add2(acc[ri][j], uS[(0 * 32 + ri * 4 + j) * NTHR + tid]),
                            lo, hi);
                    v[ri][2 * j]     = fast_tanh(lo);
                    v[ri][2 * j + 1] = fast_tanh(hi);
                }
#pragma unroll
            for (int c = 0; c < 8; ++c) {
                float4 s_lo = *reinterpret_cast<const float4*>(cur + (c0 + c) * 64 + r0);
                float4 s_hi = *reinterpret_cast<const float4*>(cur + (c0 + c) * 64 + r0 + 4);
                *reinterpret_cast<float4*>(nxt + (c0 + c) * 64 + r0) =
                    make_float4(s_lo.x * v[0][c], s_lo.y * v[1][c],
                                s_lo.z * v[2][c], s_lo.w * v[3][c]);
                *reinterpret_cast<float4*>(nxt + (c0 + c) * 64 + r0 + 4) =
                    make_float4(s_hi.x * v[4][c], s_hi.y * v[5][c],
                                s_hi.z * v[6][c], s_hi.w * v[7][c]);
            }
        }

        // ---- G = tanh(ug + S@Wsg); S_new = (1-G)*H + (Z*S) -> nxt ----
        gemmT8x8<HIDDEN>(cur, r0, Wsg_w, Wsg_b, c0, acc);
        {
            float g[8][8], h[8][8];
#pragma unroll
            for (int ri = 0; ri < 8; ++ri)
#pragma unroll
                for (int j = 0; j < 4; ++j) {
                    float lo, hi;
                    unpack2(add2(acc[ri][j], uS[(1 * 32 + ri * 4 + j) * NTHR + tid]),
                            lo, hi);
                    g[ri][2 * j]     = fast_tanh(lo);
                    g[ri][2 * j + 1] = fast_tanh(hi);
                    unpack2(H[ri][j], h[ri][2 * j], h[ri][2 * j + 1]);
                }
#pragma unroll
            for (int c = 0; c < 8; ++c) {
                float4 zs_lo = *reinterpret_cast<const float4*>(nxt + (c0 + c) * 64 + r0);
                float4 zs_hi = *reinterpret_cast<const float4*>(nxt + (c0 + c) * 64 + r0 + 4);
                *reinterpret_cast<float4*>(nxt + (c0 + c) * 64 + r0) =
                    make_float4((1.0f - g[0][c]) * h[0][c] + zs_lo.x,
                                (1.0f - g[1][c]) * h[1][c] + zs_lo.y,
                                (1.0f - g[2][c]) * h[2][c] + zs_lo.z,
                                (1.0f - g[3][c]) * h[3][c] + zs_lo.w);
                *reinterpret_cast<float4*>(nxt + (c0 + c) * 64 + r0 + 4) =
                    make_float4((1.0f - g[4][c]) * h[4][c] + zs_hi.x,
                                (1.0f - g[5][c]) * h[5][c] + zs_hi.y,
                                (1.0f - g[6][c]) * h[6][c] + zs_hi.z,
                                (1.0f - g[7][c]) * h[7][c] + zs_hi.w);
            }
        }
        // swap buffers
        float* tmp = cur; cur = nxt; nxt = tmp;
        __syncthreads();  // new S visible to all
    }

    // ---- final: out = S @ Wf + bf ----
    if (tid < TM) {
        float s = 0.0f;
#pragma unroll 8
        for (int k = 0; k < HIDDEN; ++k) s += cur[k * 64 + tid] * Wf_w[k];
        out[row0_g + tid] = s + Wf_b[0];
    }
}

extern "C" void kernel_launch(void* const* d_in, const int* in_sizes, int n_in,
                              void* d_out, int out_size) {
    const float* x     = (const float*)d_in[0];
    const float* t     = (const float*)d_in[1];
    const float* Sw_w  = (const float*)d_in[2];
    const float* Sw_b  = (const float*)d_in[3];
    const float* Uz_w  = (const float*)d_in[4];
    const float* Uz_b  = (const float*)d_in[5];
    const float* Wsz_w = (const float*)d_in[6];
    const float* Wsz_b = (const float*)d_in[7];
    const float* Ug_w  = (const float*)d_in[8];
    const float* Ug_b  = (const float*)d_in[9];
    const float* Wsg_w = (const float*)d_in[10];
    const float* Wsg_b = (const float*)d_in[11];
    const float* Ur_w  = (const float*)d_in[12];
    const float* Ur_b  = (const float*)d_in[13];
    const float* Wsr_w = (const float*)d_in[14];
    const float* Wsr_b = (const float*)d_in[15];
    const float* Uh_w  = (const float*)d_in[16];
    const float* Uh_b  = (const float*)d_in[17];
    const float* Wsh_w = (const float*)d_in[18];
    const float* Wsh_b = (const float*)d_in[19];
    const float* Wf_w  = (const float*)d_in[20];
    const float* Wf_b  = (const float*)d_in[21];
    const int*   nlp   = (const int*)d_in[22];
    float* out = (float*)d_out;

    const int B = in_sizes[0] / XDIM;  // 262144
    const int nblocks = B / TM;        // 4096

    static bool attr_set = false;
    if (!attr_set) {
        cudaFuncSetAttribute(dgm_fused_kernel,
                             cudaFuncAttributeMaxDynamicSharedMemorySize, SMEM_TOTAL);
        attr_set = true;
    }
    dgm_fused_kernel<<<nblocks, NTHR, SMEM_TOTAL>>>(
        x, t, Sw_w, Sw_b, Uz_w, Uz_b, Wsz_w, Wsz_b, Ug_w, Ug_b, Wsg_w, Wsg_b,
        Ur_w, Ur_b, Wsr_w, Wsr_b, Uh_w, Uh_b, Wsh_w, Wsh_b, Wf_w, Wf_b, nlp, out);
}

// round 9
// speedup vs baseline: 2.9139x; 2.9139x over previous
#include <cuda_runtime.h>

// Fused DGM network, R8.
// TM=32 rows/CTA, 128 threads, per-thread 4 rows x 8 cols.
// Key ideas (from R6/R7 ncu evidence):
//  * LDG charges L1 per-lane bytes (no broadcast dedup) -> move W into SMEM
//    via double-buffered cp.async chunks; LDS broadcasts are free, so the
//    crossbar cost drops to 3 phases per warp-k (A 1 + W 2), ~0.7ms floor.
//  * u-projections live in a __device__ global scratch (512MB), freeing SMEM
//    and registers; their traffic is 0.03 B/MAC.
//  * XT tile aliases the SR buffer (dead after phase 1). SMEM = 64KB/CTA ->
//    3 CTAs/SM = 12 warps (3/SMSP); reg budget 170 (est ~150, no H blow-up).
//  * All data hazards are covered by the per-chunk __syncthreads inside the
//    staged GEMM (uniform control flow), so the layer loop needs no extra
//    barriers.

namespace {
constexpr int XDIM   = 100;
constexpr int XTDIM  = 101;
constexpr int HIDDEN = 128;
constexpr int TM     = 32;
constexpr int NTHR   = 128;
constexpr int NBLK   = 8192;   // 262144 / TM

// smem: [0,16K) S buffer [128][32]; [16K,32K) SR buffer (aliases XT);
//       [32K,64K) W staging, 2 x 32x128 floats.
constexpr int OFF_S      = 0;
constexpr int OFF_SR     = 16384;
constexpr int OFF_W      = 32768;
constexpr int SMEM_TOTAL = 65536;
}

using ull = unsigned long long;

// u-projection scratch: [block][plane(4)][slot(16)][tid(128)] packed f32x2.
__device__ ull g_u[(size_t)NBLK * 4 * 16 * NTHR];

__device__ __forceinline__ ull pack2(float lo, float hi) {
    ull r;
    asm("mov.b64 %0, {%1, %2};" : "=l"(r) : "f"(lo), "f"(hi));
    return r;
}
__device__ __forceinline__ void unpack2(ull v, float& lo, float& hi) {
    asm("mov.b64 {%0, %1}, %2;" : "=f"(lo), "=f"(hi) : "l"(v));
}
__device__ __forceinline__ void fma2(ull& d, ull a, ull b) {
    asm("fma.rn.f32x2 %0, %1, %2, %0;" : "+l"(d) : "l"(a), "l"(b));
}
__device__ __forceinline__ ull add2(ull a, ull b) {
    ull d;
    asm("add.rn.f32x2 %0, %1, %2;" : "=l"(d) : "l"(a), "l"(b));
    return d;
}

// tanh via exp: ~1e-7 abs error, saturates correctly at +/-inf.
__device__ __forceinline__ float fast_tanh(float v) {
    float e = __expf(2.0f * v);
    return 1.0f - __fdividef(2.0f, e + 1.0f);
}

// Copy n16 x 16B from global to shared with cp.async; always commits a group.
__device__ __forceinline__ void cp_chunk(float* sdst, const float* gsrc,
                                         int n16, int tid) {
    unsigned sb = (unsigned)__cvta_generic_to_shared(sdst);
    for (int u = tid; u < n16; u += NTHR) {
        asm volatile("cp.async.cg.shared.global [%0], [%1], 16;"
                     :: "r"(sb + u * 16), "l"(gsrc + (size_t)u * 4) : "memory");
    }
    asm volatile("cp.async.commit_group;" ::: "memory");
}

// acc[4][4] (f32x2 col-pairs) = bias[c0..c0+8) +
//   A[r0..r0+4)[0..K) @ W[0..K)[c0..c0+8)
// A transposed in shared [K][32] (row-stride 32 = conflict-free float4).
// W streamed through 2 SMEM chunk buffers (32 k-rows each) via cp.async.
// Contains __syncthreads per chunk -> must be called uniformly by all threads.
template <int K>
__device__ __forceinline__ void gemm_staged(const float* __restrict__ sA,
                                            const float* __restrict__ gW,
                                            const float* __restrict__ bias,
                                            float* __restrict__ sW,
                                            int tid, int r0, int c0,
                                            ull acc[4][4]) {
    constexpr int CH = (K + 31) / 32;
    {
        ulonglong2 bb0 = reinterpret_cast<const ulonglong2*>(bias + c0)[0];
        ulonglong2 bb1 = reinterpret_cast<const ulonglong2*>(bias + c0)[1];
#pragma unroll
        for (int ri = 0; ri < 4; ++ri) {
            acc[ri][0] = bb0.x; acc[ri][1] = bb0.y;
            acc[ri][2] = bb1.x; acc[ri][3] = bb1.y;
        }
    }
    // prologue: chunk 0
    cp_chunk(sW, gW, (K < 32 ? K : 32) * 32, tid);
#pragma unroll 1
    for (int ch = 0; ch < CH; ++ch) {
        asm volatile("cp.async.wait_group 0;" ::: "memory");
        __syncthreads();  // chunk ch visible to all; prev buffer fully consumed
        const int kbase = ch * 32;
        const int kcnt = (K - kbase) < 32 ? (K - kbase) : 32;
        if (ch + 1 < CH) {
            const int nb = kbase + 32;
            const int nc = (K - nb) < 32 ? (K - nb) : 32;
            cp_chunk(sW + ((ch + 1) & 1) * (32 * HIDDEN),
                     gW + (size_t)nb * HIDDEN, nc * 32, tid);
        }
        const float* wb = sW + (ch & 1) * (32 * HIDDEN);
        const float* ab = sA + kbase * TM;
#pragma unroll 4
        for (int kk = 0; kk < kcnt; ++kk) {
            float4 a = *reinterpret_cast<const float4*>(ab + kk * TM + r0);
            ulonglong2 w0 =
                *reinterpret_cast<const ulonglong2*>(wb + kk * HIDDEN + c0);
            ulonglong2 w1 =
                *reinterpret_cast<const ulonglong2*>(wb + kk * HIDDEN + c0 + 4);
            ull av;
            av = pack2(a.x, a.x);
            fma2(acc[0][0], av, w0.x); fma2(acc[0][1], av, w0.y);
            fma2(acc[0][2], av, w1.x); fma2(acc[0][3], av, w1.y);
            av = pack2(a.y, a.y);
            fma2(acc[1][0], av, w0.x); fma2(acc[1][1], av, w0.y);
            fma2(acc[1][2], av, w1.x); fma2(acc[1][3], av, w1.y);
            av = pack2(a.z, a.z);
            fma2(acc[2][0], av, w0.x); fma2(acc[2][1], av, w0.y);
            fma2(acc[2][2], av, w1.x); fma2(acc[2][3], av, w1.y);
            av = pack2(a.w, a.w);
            fma2(acc[3][0], av, w0.x); fma2(acc[3][1], av, w0.y);
            fma2(acc[3][2], av, w1.x); fma2(acc[3][3], av, w1.y);
        }
    }
}

__global__ void __launch_bounds__(NTHR, 3) dgm_fused_kernel(
    const float* __restrict__ x, const float* __restrict__ t,
    const float* __restrict__ Sw_w, const float* __restrict__ Sw_b,
    const float* __restrict__ Uz_w, const float* __restrict__ Uz_b,
    const float* __restrict__ Wsz_w, const float* __restrict__ Wsz_b,
    const float* __restrict__ Ug_w, const float* __restrict__ Ug_b,
    const float* __restrict__ Wsg_w, const float* __restrict__ Wsg_b,
    const float* __restrict__ Ur_w, const float* __restrict__ Ur_b,
    const float* __restrict__ Wsr_w, const float* __restrict__ Wsr_b,
    const float* __restrict__ Uh_w, const float* __restrict__ Uh_b,
    const float* __restrict__ Wsh_w, const float* __restrict__ Wsh_b,
    const float* __restrict__ Wf_w, const float* __restrict__ Wf_b,
    const int* __restrict__ n_layers_p, float* __restrict__ out) {
    extern __shared__ char smem[];
    float* sS  = reinterpret_cast<float*>(smem + OFF_S);   // [128][32]
    float* sSR = reinterpret_cast<float*>(smem + OFF_SR);  // [128][32]
    float* sW  = reinterpret_cast<float*>(smem + OFF_W);   // 2 x [32][128]
    float* sXT = sSR;                                      // alias, phase 1 only

    const int tid = threadIdx.x;
    const int row0_g = blockIdx.x * TM;

    // ---- stage xt (transposed): sXT[k*32 + m] = xt[m][k] ----
    {
        const float4* x4 = reinterpret_cast<const float4*>(x);  // 25 float4/row
        for (int idx = tid; idx < TM * 25; idx += NTHR) {
            int m = idx & 31;
            int q = idx >> 5;  // 0..24
            float4 v = x4[(size_t)(row0_g + m) * 25 + q];
            sXT[(q * 4 + 0) * TM + m] = v.x;
            sXT[(q * 4 + 1) * TM + m] = v.y;
            sXT[(q * 4 + 2) * TM + m] = v.z;
            sXT[(q * 4 + 3) * TM + m] = v.w;
        }
        if (tid < TM) sXT[100 * TM + tid] = t[row0_g + tid];
    }
    __syncthreads();

    // Thread tile: c0 = 8*(tid>>3) (4 distinct per warp -> W broadcast),
    //              r0 = 4*(tid&7)  (8 distinct -> A covers all 32 banks).
    const int c0 = (tid >> 3) * 8;  // 0..120
    const int r0 = (tid & 7) * 4;   // 0..28

    ull acc[4][4];
    float v[4][8];

    ull* const u0 = g_u + (((size_t)blockIdx.x * 4 + 0) * 16) * NTHR + tid;
    ull* const u1 = g_u + (((size_t)blockIdx.x * 4 + 1) * 16) * NTHR + tid;
    ull* const u2 = g_u + (((size_t)blockIdx.x * 4 + 2) * 16) * NTHR + tid;
    ull* const u3 = g_u + (((size_t)blockIdx.x * 4 + 3) * 16) * NTHR + tid;

    // ---- phase 1: S1 = tanh(xt@Sw + b) -> sS ----
    gemm_staged<XTDIM>(sXT, Sw_w, Sw_b, sW, tid, r0, c0, acc);
#pragma unroll
    for (int ri = 0; ri < 4; ++ri)
#pragma unroll
        for (int j = 0; j < 4; ++j) {
            float lo, hi;
            unpack2(acc[ri][j], lo, hi);
            v[ri][2 * j]     = fast_tanh(lo);
            v[ri][2 * j + 1] = fast_tanh(hi);
        }
#pragma unroll
    for (int cc = 0; cc < 8; ++cc)
        *reinterpret_cast<float4*>(sS + (c0 + cc) * TM + r0) =
            make_float4(v[0][cc], v[1][cc], v[2][cc], v[3][cc]);

    // ---- u-projections (pre-activation, with bias) -> global scratch ----
    gemm_staged<XTDIM>(sXT, Uz_w, Uz_b, sW, tid, r0, c0, acc);
#pragma unroll
    for (int ri = 0; ri < 4; ++ri)
#pragma unroll
        for (int j = 0; j < 4; ++j) u0[(size_t)(ri * 4 + j) * NTHR] = acc[ri][j];
    gemm_staged<XTDIM>(sXT, Ug_w, Ug_b, sW, tid, r0, c0, acc);
#pragma unroll
    for (int ri = 0; ri < 4; ++ri)
#pragma unroll
        for (int j = 0; j < 4; ++j) u1[(size_t)(ri * 4 + j) * NTHR] = acc[ri][j];
    gemm_staged<XTDIM>(sXT, Ur_w, Ur_b, sW, tid, r0, c0, acc);
#pragma unroll
    for (int ri = 0; ri < 4; ++ri)
#pragma unroll
        for (int j = 0; j < 4; ++j) u2[(size_t)(ri * 4 + j) * NTHR] = acc[ri][j];
    gemm_staged<XTDIM>(sXT, Uh_w, Uh_b, sW, tid, r0, c0, acc);
#pragma unroll
    for (int ri = 0; ri < 4; ++ri)
#pragma unroll
        for (int j = 0; j < 4; ++j) u3[(size_t)(ri * 4 + j) * NTHR] = acc[ri][j];

    const int nl = *n_layers_p;
    float* cur = sS;   // S lives here
    float* nxt = sSR;  // scratch (XT is dead from here on)

#pragma unroll 1
    for (int l = 1; l < nl; ++l) {
        // ---- R = tanh(ur + S@Wsr); nxt = S * R ----
        // (the GEMM's internal chunk-0 barrier orders prior epilogue writes)
        gemm_staged<HIDDEN>(cur, Wsr_w, Wsr_b, sW, tid, r0, c0, acc);
#pragma unroll
        for (int ri = 0; ri < 4; ++ri)
#pragma unroll
            for (int j = 0; j < 4; ++j) {
                float lo, hi;
                unpack2(add2(acc[ri][j], u2[(size_t)(ri * 4 + j) * NTHR]), lo, hi);
                v[ri][2 * j]     = fast_tanh(lo);
                v[ri][2 * j + 1] = fast_tanh(hi);
            }
#pragma unroll
        for (int cc = 0; cc < 8; ++cc) {
            float4 s4 = *reinterpret_cast<const float4*>(cur + (c0 + cc) * TM + r0);
            *reinterpret_cast<float4*>(nxt + (c0 + cc) * TM + r0) =
                make_float4(s4.x * v[0][cc], s4.y * v[1][cc],
                            s4.z * v[2][cc], s4.w * v[3][cc]);
        }

        // ---- H = uh + SR@Wsh + bh (kept packed in 32 regs) ----
        ull H[4][4];
        gemm_staged<HIDDEN>(nxt, Wsh_w, Wsh_b, sW, tid, r0, c0, acc);
#pragma unroll
        for (int ri = 0; ri < 4; ++ri)
#pragma unroll
            for (int j = 0; j < 4; ++j)
                H[ri][j] = add2(acc[ri][j], u3[(size_t)(ri * 4 + j) * NTHR]);

        // ---- Z = tanh(uz + S@Wsz); nxt = Z * S (own slots) ----
        // (Z-GEMM's internal barriers guarantee all H reads of nxt are done
        //  before any thread's Z epilogue overwrites it)
        gemm_staged<HIDDEN>(cur, Wsz_w, Wsz_b, sW, tid, r0, c0, acc);
#pragma unroll
        for (int ri = 0; ri < 4; ++ri)
#pragma unroll
            for (int j = 0; j < 4; ++j) {
                float lo, hi;
                unpack2(add2(acc[ri][j], u0[(size_t)(ri * 4 + j) * NTHR]), lo, hi);
                v[ri][2 * j]     = fast_tanh(lo);
                v[ri][2 * j + 1] = fast_tanh(hi);
            }
#pragma unroll
        for (int cc = 0; cc < 8; ++cc) {
            float4 s4 = *reinterpret_cast<const float4*>(cur + (c0 + cc) * TM + r0);
            *reinterpret_cast<float4*>(nxt + (c0 + cc) * TM + r0) =
                make_float4(s4.x * v[0][cc], s4.y * v[1][cc],
                            s4.z * v[2][cc], s4.w * v[3][cc]);
        }

        // ---- G = tanh(ug + S@Wsg); S_new = (1-G)*H + (Z*S) -> nxt ----
        gemm_staged<HIDDEN>(cur, Wsg_w, Wsg_b, sW, tid, r0, c0, acc);
        {
            float h[4][8];
#pragma unroll
            for (int ri = 0; ri < 4; ++ri)
#pragma unroll
                for (int j = 0; j < 4; ++j) {
                    float lo, hi;
                    unpack2(add2(acc[ri][j], u1[(size_t)(ri * 4 + j) * NTHR]),
                            lo, hi);
                    v[ri][2 * j]     = fast_tanh(lo);
                    v[ri][2 * j + 1] = fast_tanh(hi);
                    unpack2(H[ri][j], h[ri][2 * j], h[ri][2 * j + 1]);
                }
#pragma unroll
            for (int cc = 0; cc < 8; ++cc) {
                float4 zs = *reinterpret_cast<const float4*>(nxt + (c0 + cc) * TM + r0);
                *reinterpret_cast<float4*>(nxt + (c0 + cc) * TM + r0) =
                    make_float4((1.0f - v[0][cc]) * h[0][cc] + zs.x,
                                (1.0f - v[1][cc]) * h[1][cc] + zs.y,
                                (1.0f - v[2][cc]) * h[2][cc] + zs.z,
                                (1.0f - v[3][cc]) * h[3][cc] + zs.w);
            }
        }
        float* tmp = cur; cur = nxt; nxt = tmp;
    }

    // ---- final: out = S @ Wf + bf ----
    __syncthreads();
    {
        const int w = tid >> 5, lane = tid & 31;
        float s = 0.0f;
#pragma unroll 8
        for (int k = 0; k < 32; ++k)
            s += cur[(w * 32 + k) * TM + lane] * Wf_w[w * 32 + k];
        sW[w * 32 + lane] = s;  // sW free as reduction scratch
        __syncthreads();
        if (tid < TM)
            out[row0_g + tid] =
                sW[tid] + sW[32 + tid] + sW[64 + tid] + sW[96 + tid] + Wf_b[0];
    }
}

extern "C" void kernel_launch(void* const* d_in, const int* in_sizes, int n_in,
                              void* d_out, int out_size) {
    const float* x     = (const float*)d_in[0];
    const float* t     = (const float*)d_in[1];
    const float* Sw_w  = (const float*)d_in[2];
    const float* Sw_b  = (const float*)d_in[3];
    const float* Uz_w  = (const float*)d_in[4];
    const float* Uz_b  = (const float*)d_in[5];
    const float* Wsz_w = (const float*)d_in[6];
    const float* Wsz_b = (const float*)d_in[7];
    const float* Ug_w  = (const float*)d_in[8];
    const float* Ug_b  = (const float*)d_in[9];
    const float* Wsg_w = (const float*)d_in[10];
    const float* Wsg_b = (const float*)d_in[11];
    const float* Ur_w  = (const float*)d_in[12];
    const float* Ur_b  = (const float*)d_in[13];
    const float* Wsr_w = (const float*)d_in[14];
    const float* Wsr_b = (const float*)d_in[15];
    const float* Uh_w  = (const float*)d_in[16];
    const float* Uh_b  = (const float*)d_in[17];
    const float* Wsh_w = (const float*)d_in[18];
    const float* Wsh_b = (const float*)d_in[19];
    const float* Wf_w  = (const float*)d_in[20];
    const float* Wf_b  = (const float*)d_in[21];
    const int*   nlp   = (const int*)d_in[22];
    float* out = (float*)d_out;

    const int B = in_sizes[0] / XDIM;  // 262144
    const int nblocks = B / TM;        // 8192

    static bool attr_set = false;
    if (!attr_set) {
        cudaFuncSetAttribute(dgm_fused_kernel,
                             cudaFuncAttributeMaxDynamicSharedMemorySize,
                             SMEM_TOTAL);
        attr_set = true;
    }
    dgm_fused_kernel<<<nblocks, NTHR, SMEM_TOTAL>>>(
        x, t, Sw_w, Sw_b, Uz_w, Uz_b, Wsz_w, Wsz_b, Ug_w, Ug_b, Wsg_w, Wsg_b,
        Ur_w, Ur_b, Wsr_w, Wsr_b, Uh_w, Uh_b, Wsh_w, Wsh_b, Wf_w, Wf_b, nlp, out);
}

// round 10
// speedup vs baseline: 2.9169x; 1.0010x over previous
#include <cuda_runtime.h>

// Fused DGM network, R8.
// TM=32 rows/CTA, 128 threads, per-thread 4 rows x 8 cols.
// Key ideas (from R6/R7 ncu evidence):
//  * LDG charges L1 per-lane bytes (no broadcast dedup) -> move W into SMEM
//    via double-buffered cp.async chunks; LDS broadcasts are free, so the
//    crossbar cost drops to 3 phases per warp-k (A 1 + W 2), ~0.7ms floor.
//  * u-projections live in a __device__ global scratch (512MB), freeing SMEM
//    and registers; their traffic is 0.03 B/MAC.
//  * XT tile aliases the SR buffer (dead after phase 1). SMEM = 64KB/CTA ->
//    3 CTAs/SM = 12 warps (3/SMSP); reg budget 170 (est ~150, no H blow-up).
//  * All data hazards are covered by the per-chunk __syncthreads inside the
//    staged GEMM (uniform control flow), so the layer loop needs no extra
//    barriers.

namespace {
constexpr int XDIM   = 100;
constexpr int XTDIM  = 101;
constexpr int HIDDEN = 128;
constexpr int TM     = 32;
constexpr int NTHR   = 128;
constexpr int NBLK   = 8192;   // 262144 / TM

// smem: [0,16K) S buffer [128][32]; [16K,32K) SR buffer (aliases XT);
//       [32K,64K) W staging, 2 x 32x128 floats.
constexpr int OFF_S      = 0;
constexpr int OFF_SR     = 16384;
constexpr int OFF_W      = 32768;
constexpr int SMEM_TOTAL = 65536;
}

using ull = unsigned long long;

// u-projection scratch: [block][plane(4)][slot(16)][tid(128)] packed f32x2.
__device__ ull g_u[(size_t)NBLK * 4 * 16 * NTHR];

__device__ __forceinline__ ull pack2(float lo, float hi) {
    ull r;
    asm("mov.b64 %0, {%1, %2};" : "=l"(r) : "f"(lo), "f"(hi));
    return r;
}
__device__ __forceinline__ void unpack2(ull v, float& lo, float& hi) {
    asm("mov.b64 {%0, %1}, %2;" : "=f"(lo), "=f"(hi) : "l"(v));
}
__device__ __forceinline__ void fma2(ull& d, ull a, ull b) {
    asm("fma.rn.f32x2 %0, %1, %2, %0;" : "+l"(d) : "l"(a), "l"(b));
}
__device__ __forceinline__ ull add2(ull a, ull b) {
    ull d;
    asm("add.rn.f32x2 %0, %1, %2;" : "=l"(d) : "l"(a), "l"(b));
    return d;
}

// tanh via exp: ~1e-7 abs error, saturates correctly at +/-inf.
__device__ __forceinline__ float fast_tanh(float v) {
    float e = __expf(2.0f * v);
    return 1.0f - __fdividef(2.0f, e + 1.0f);
}

// Copy n16 x 16B from global to shared with cp.async; always commits a group.
__device__ __forceinline__ void cp_chunk(float* sdst, const float* gsrc,
                                         int n16, int tid) {
    unsigned sb = (unsigned)__cvta_generic_to_shared(sdst);
    for (int u = tid; u < n16; u += NTHR) {
        asm volatile("cp.async.cg.shared.global [%0], [%1], 16;"
                     :: "r"(sb + u * 16), "l"(gsrc + (size_t)u * 4) : "memory");
    }
    asm volatile("cp.async.commit_group;" ::: "memory");
}

// acc[4][4] (f32x2 col-pairs) = bias[c0..c0+8) +
//   A[r0..r0+4)[0..K) @ W[0..K)[c0..c0+8)
// A transposed in shared [K][32] (row-stride 32 = conflict-free float4).
// W streamed through 2 SMEM chunk buffers (32 k-rows each) via cp.async.
// Contains __syncthreads per chunk -> must be called uniformly by all threads.
template <int K>
__device__ __forceinline__ void gemm_staged(const float* __restrict__ sA,
                                            const float* __restrict__ gW,
                                            const float* __restrict__ bias,
                                            float* __restrict__ sW,
                                            int tid, int r0, int c0,
                                            ull acc[4][4]) {
    constexpr int CH = (K + 31) / 32;
    {
        ulonglong2 bb0 = reinterpret_cast<const ulonglong2*>(bias + c0)[0];
        ulonglong2 bb1 = reinterpret_cast<const ulonglong2*>(bias + c0)[1];
#pragma unroll
        for (int ri = 0; ri < 4; ++ri) {
            acc[ri][0] = bb0.x; acc[ri][1] = bb0.y;
            acc[ri][2] = bb1.x; acc[ri][3] = bb1.y;
        }
    }
    // prologue: chunk 0
    cp_chunk(sW, gW, (K < 32 ? K : 32) * 32, tid);
#pragma unroll 1
    for (int ch = 0; ch < CH; ++ch) {
        asm volatile("cp.async.wait_group 0;" ::: "memory");
        __syncthreads();  // chunk ch visible to all; prev buffer fully consumed
        const int kbase = ch * 32;
        const int kcnt = (K - kbase) < 32 ? (K - kbase) : 32;
        if (ch + 1 < CH) {
            const int nb = kbase + 32;
            const int nc = (K - nb) < 32 ? (K - nb) : 32;
            cp_chunk(sW + ((ch + 1) & 1) * (32 * HIDDEN),
                     gW + (size_t)nb * HIDDEN, nc * 32, tid);
        }
        const float* wb = sW + (ch & 1) * (32 * HIDDEN);
        const float* ab = sA + kbase * TM;
#pragma unroll 4
        for (int kk = 0; kk < kcnt; ++kk) {
            float4 a = *reinterpret_cast<const float4*>(ab + kk * TM + r0);
            ulonglong2 w0 =
                *reinterpret_cast<const ulonglong2*>(wb + kk * HIDDEN + c0);
            ulonglong2 w1 =
                *reinterpret_cast<const ulonglong2*>(wb + kk * HIDDEN + c0 + 4);
            ull av;
            av = pack2(a.x, a.x);
            fma2(acc[0][0], av, w0.x); fma2(acc[0][1], av, w0.y);
            fma2(acc[0][2], av, w1.x); fma2(acc[0][3], av, w1.y);
            av = pack2(a.y, a.y);
            fma2(acc[1][0], av, w0.x); fma2(acc[1][1], av, w0.y);
            fma2(acc[1][2], av, w1.x); fma2(acc[1][3], av, w1.y);
            av = pack2(a.z, a.z);
            fma2(acc[2][0], av, w0.x); fma2(acc[2][1], av, w0.y);
            fma2(acc[2][2], av, w1.x); fma2(acc[2][3], av, w1.y);
            av = pack2(a.w, a.w);
            fma2(acc[3][0], av, w0.x); fma2(acc[3][1], av, w0.y);
            fma2(acc[3][2], av, w1.x); fma2(acc[3][3], av, w1.y);
        }
    }
}

__global__ void __launch_bounds__(NTHR, 3) dgm_fused_kernel(
    const float* __restrict__ x, const float* __restrict__ t,
    const float* __restrict__ Sw_w, const float* __restrict__ Sw_b,
    const float* __restrict__ Uz_w, const float* __restrict__ Uz_b,
    const float* __restrict__ Wsz_w, const float* __restrict__ Wsz_b,
    const float* __restrict__ Ug_w, const float* __restrict__ Ug_b,
    const float* __restrict__ Wsg_w, const float* __restrict__ Wsg_b,
    const float* __restrict__ Ur_w, const float* __restrict__ Ur_b,
    const float* __restrict__ Wsr_w, const float* __restrict__ Wsr_b,
    const float* __restrict__ Uh_w, const float* __restrict__ Uh_b,
    const float* __restrict__ Wsh_w, const float* __restrict__ Wsh_b,
    const float* __restrict__ Wf_w, const float* __restrict__ Wf_b,
    const int* __restrict__ n_layers_p, float* __restrict__ out) {
    extern __shared__ char smem[];
    float* sS  = reinterpret_cast<float*>(smem + OFF_S);   // [128][32]
    float* sSR = reinterpret_cast<float*>(smem + OFF_SR);  // [128][32]
    float* sW  = reinterpret_cast<float*>(smem + OFF_W);   // 2 x [32][128]
    float* sXT = sSR;                                      // alias, phase 1 only

    const int tid = threadIdx.x;
    const int row0_g = blockIdx.x * TM;

    // ---- stage xt (transposed): sXT[k*32 + m] = xt[m][k] ----
    {
        const float4* x4 = reinterpret_cast<const float4*>(x);  // 25 float4/row
        for (int idx = tid; idx < TM * 25; idx += NTHR) {
            int m = idx & 31;
            int q = idx >> 5;  // 0..24
            float4 v = x4[(size_t)(row0_g + m) * 25 + q];
            sXT[(q * 4 + 0) * TM + m] = v.x;
            sXT[(q * 4 + 1) * TM + m] = v.y;
            sXT[(q * 4 + 2) * TM + m] = v.z;
            sXT[(q * 4 + 3) * TM + m] = v.w;
        }
        if (tid < TM) sXT[100 * TM + tid] = t[row0_g + tid];
    }
    __syncthreads();

    // Thread tile: c0 = 8*(tid>>3) (4 distinct per warp -> W broadcast),
    //              r0 = 4*(tid&7)  (8 distinct -> A covers all 32 banks).
    const int c0 = (tid >> 3) * 8;  // 0..120
    const int r0 = (tid & 7) * 4;   // 0..28

    ull acc[4][4];
    float v[4][8];

    ull* const u0 = g_u + (((size_t)blockIdx.x * 4 + 0) * 16) * NTHR + tid;
    ull* const u1 = g_u + (((size_t)blockIdx.x * 4 + 1) * 16) * NTHR + tid;
    ull* const u2 = g_u + (((size_t)blockIdx.x * 4 + 2) * 16) * NTHR + tid;
    ull* const u3 = g_u + (((size_t)blockIdx.x * 4 + 3) * 16) * NTHR + tid;

    // ---- phase 1: S1 = tanh(xt@Sw + b) -> sS ----
    gemm_staged<XTDIM>(sXT, Sw_w, Sw_b, sW, tid, r0, c0, acc);
#pragma unroll
    for (int ri = 0; ri < 4; ++ri)
#pragma unroll
        for (int j = 0; j < 4; ++j) {
            float lo, hi;
            unpack2(acc[ri][j], lo, hi);
            v[ri][2 * j]     = fast_tanh(lo);
            v[ri][2 * j + 1] = fast_tanh(hi);
        }
#pragma unroll
    for (int cc = 0; cc < 8; ++cc)
        *reinterpret_cast<float4*>(sS + (c0 + cc) * TM + r0) =
            make_float4(v[0][cc], v[1][cc], v[2][cc], v[3][cc]);

    // ---- u-projections (pre-activation, with bias) -> global scratch ----
    gemm_staged<XTDIM>(sXT, Uz_w, Uz_b, sW, tid, r0, c0, acc);
#pragma unroll
    for (int ri = 0; ri < 4; ++ri)
#pragma unroll
        for (int j = 0; j < 4; ++j) u0[(size_t)(ri * 4 + j) * NTHR] = acc[ri][j];
    gemm_staged<XTDIM>(sXT, Ug_w, Ug_b, sW, tid, r0, c0, acc);
#pragma unroll
    for (int ri = 0; ri < 4; ++ri)
#pragma unroll
        for (int j = 0; j < 4; ++j) u1[(size_t)(ri * 4 + j) * NTHR] = acc[ri][j];
    gemm_staged<XTDIM>(sXT, Ur_w, Ur_b, sW, tid, r0, c0, acc);
#pragma unroll
    for (int ri = 0; ri < 4; ++ri)
#pragma unroll
        for (int j = 0; j < 4; ++j) u2[(size_t)(ri * 4 + j) * NTHR] = acc[ri][j];
    gemm_staged<XTDIM>(sXT, Uh_w, Uh_b, sW, tid, r0, c0, acc);
#pragma unroll
    for (int ri = 0; ri < 4; ++ri)
#pragma unroll
        for (int j = 0; j < 4; ++j) u3[(size_t)(ri * 4 + j) * NTHR] = acc[ri][j];

    const int nl = *n_layers_p;
    float* cur = sS;   // S lives here
    float* nxt = sSR;  // scratch (XT is dead from here on)

#pragma unroll 1
    for (int l = 1; l < nl; ++l) {
        // ---- R = tanh(ur + S@Wsr); nxt = S * R ----
        // (the GEMM's internal chunk-0 barrier orders prior epilogue writes)
        gemm_staged<HIDDEN>(cur, Wsr_w, Wsr_b, sW, tid, r0, c0, acc);
#pragma unroll
        for (int ri = 0; ri < 4; ++ri)
#pragma unroll
            for (int j = 0; j < 4; ++j) {
                float lo, hi;
                unpack2(add2(acc[ri][j], u2[(size_t)(ri * 4 + j) * NTHR]), lo, hi);
                v[ri][2 * j]     = fast_tanh(lo);
                v[ri][2 * j + 1] = fast_tanh(hi);
            }
#pragma unroll
        for (int cc = 0; cc < 8; ++cc) {
            float4 s4 = *reinterpret_cast<const float4*>(cur + (c0 + cc) * TM + r0);
            *reinterpret_cast<float4*>(nxt + (c0 + cc) * TM + r0) =
                make_float4(s4.x * v[0][cc], s4.y * v[1][cc],
                            s4.z * v[2][cc], s4.w * v[3][cc]);
        }

        // ---- H = uh + SR@Wsh + bh (kept packed in 32 regs) ----
        ull H[4][4];
        gemm_staged<HIDDEN>(nxt, Wsh_w, Wsh_b, sW, tid, r0, c0, acc);
#pragma unroll
        for (int ri = 0; ri < 4; ++ri)
#pragma unroll
            for (int j = 0; j < 4; ++j)
                H[ri][j] = add2(acc[ri][j], u3[(size_t)(ri * 4 + j) * NTHR]);

        // ---- Z = tanh(uz + S@Wsz); nxt = Z * S (own slots) ----
        // (Z-GEMM's internal barriers guarantee all H reads of nxt are done
        //  before any thread's Z epilogue overwrites it)
        gemm_staged<HIDDEN>(cur, Wsz_w, Wsz_b, sW, tid, r0, c0, acc);
#pragma unroll
        for (int ri = 0; ri < 4; ++ri)
#pragma unroll
            for (int j = 0; j < 4; ++j) {
                float lo, hi;
                unpack2(add2(acc[ri][j], u0[(size_t)(ri * 4 + j) * NTHR]), lo, hi);
                v[ri][2 * j]     = fast_tanh(lo);
                v[ri][2 * j + 1] = fast_tanh(hi);
            }
#pragma unroll
        for (int cc = 0; cc < 8; ++cc) {
            float4 s4 = *reinterpret_cast<const float4*>(cur + (c0 + cc) * TM + r0);
            *reinterpret_cast<float4*>(nxt + (c0 + cc) * TM + r0) =
                make_float4(s4.x * v[0][cc], s4.y * v[1][cc],
                            s4.z * v[2][cc], s4.w * v[3][cc]);
        }

        // ---- G = tanh(ug + S@Wsg); S_new = (1-G)*H + (Z*S) -> nxt ----
        gemm_staged<HIDDEN>(cur, Wsg_w, Wsg_b, sW, tid, r0, c0, acc);
        {
            float h[4][8];
#pragma unroll
            for (int ri = 0; ri < 4; ++ri)
#pragma unroll
                for (int j = 0; j < 4; ++j) {
                    float lo, hi;
                    unpack2(add2(acc[ri][j], u1[(size_t)(ri * 4 + j) * NTHR]),
                            lo, hi);
                    v[ri][2 * j]     = fast_tanh(lo);
                    v[ri][2 * j + 1] = fast_tanh(hi);
                    unpack2(H[ri][j], h[ri][2 * j], h[ri][2 * j + 1]);
                }
#pragma unroll
            for (int cc = 0; cc < 8; ++cc) {
                float4 zs = *reinterpret_cast<const float4*>(nxt + (c0 + cc) * TM + r0);
                *reinterpret_cast<float4*>(nxt + (c0 + cc) * TM + r0) =
                    make_float4((1.0f - v[0][cc]) * h[0][cc] + zs.x,
                                (1.0f - v[1][cc]) * h[1][cc] + zs.y,
                                (1.0f - v[2][cc]) * h[2][cc] + zs.z,
                                (1.0f - v[3][cc]) * h[3][cc] + zs.w);
            }
        }
        float* tmp = cur; cur = nxt; nxt = tmp;
    }

    // ---- final: out = S @ Wf + bf ----
    __syncthreads();
    {
        const int w = tid >> 5, lane = tid & 31;
        float s = 0.0f;
#pragma unroll 8
        for (int k = 0; k < 32; ++k)
            s += cur[(w * 32 + k) * TM + lane] * Wf_w[w * 32 + k];
        sW[w * 32 + lane] = s;  // sW free as reduction scratch
        __syncthreads();
        if (tid < TM)
            out[row0_g + tid] =
                sW[tid] + sW[32 + tid] + sW[64 + tid] + sW[96 + tid] + Wf_b[0];
    }
}

extern "C" void kernel_launch(void* const* d_in, const int* in_sizes, int n_in,
                              void* d_out, int out_size) {
    const float* x     = (const float*)d_in[0];
    const float* t     = (const float*)d_in[1];
    const float* Sw_w  = (const float*)d_in[2];
    const float* Sw_b  = (const float*)d_in[3];
    const float* Uz_w  = (const float*)d_in[4];
    const float* Uz_b  = (const float*)d_in[5];
    const float* Wsz_w = (const float*)d_in[6];
    const float* Wsz_b = (const float*)d_in[7];
    const float* Ug_w  = (const float*)d_in[8];
    const float* Ug_b  = (const float*)d_in[9];
    const float* Wsg_w = (const float*)d_in[10];
    const float* Wsg_b = (const float*)d_in[11];
    const float* Ur_w  = (const float*)d_in[12];
    const float* Ur_b  = (const float*)d_in[13];
    const float* Wsr_w = (const float*)d_in[14];
    const float* Wsr_b = (const float*)d_in[15];
    const float* Uh_w  = (const float*)d_in[16];
    const float* Uh_b  = (const float*)d_in[17];
    const float* Wsh_w = (const float*)d_in[18];
    const float* Wsh_b = (const float*)d_in[19];
    const float* Wf_w  = (const float*)d_in[20];
    const float* Wf_b  = (const float*)d_in[21];
    const int*   nlp   = (const int*)d_in[22];
    float* out = (float*)d_out;

    const int B = in_sizes[0] / XDIM;  // 262144
    const int nblocks = B / TM;        // 8192

    static bool attr_set = false;
    if (!attr_set) {
        cudaFuncSetAttribute(dgm_fused_kernel,
                             cudaFuncAttributeMaxDynamicSharedMemorySize,
                             SMEM_TOTAL);
        attr_set = true;
    }
    dgm_fused_kernel<<<nblocks, NTHR, SMEM_TOTAL>>>(
        x, t, Sw_w, Sw_b, Uz_w, Uz_b, Wsz_w, Wsz_b, Ug_w, Ug_b, Wsg_w, Wsg_b,
        Ur_w, Ur_b, Wsr_w, Wsr_b, Uh_w, Uh_b, Wsh_w, Wsh_b, Wf_w, Wf_b, nlp, out);
}

// round 12
// speedup vs baseline: 4.6645x; 1.5991x over previous
#include <cuda_runtime.h>
#include <cuda_bf16.h>
#include <cstdint>

// R11: fused DGM on classic tensor cores (mma.sync.m16n8k16 bf16, sm_80+ PTX,
// no 'a'-gated features). bf16 hi/lo split => 3 MMAs per GEMM, fp32-class
// accuracy. TM=64 rows/CTA, 256 threads, warp = m16 x n64 tile.
// W gates staged via double-buffered cp.async (overlapped with MMA);
// u-projections (bias-folded) in fp32 global scratch.

namespace {
constexpr int XD   = 100;
constexpr int HID  = 128;
constexpr int TM   = 64;
constexpr int NTHR = 256;
constexpr int NBLK = 4096;          // 262144 / TM

constexpr int LDT    = 272;         // bytes per tile row (136 bf16), 17*16
constexpr int S_TILE = 64 * LDT;    // 17408
constexpr int W_TILE = 128 * LDT;   // 34816
constexpr int W_PAIR = 2 * W_TILE;  // 69632

constexpr int OFF_S  = 0;                    // S hi | lo
constexpr int OFF_SR = 2 * S_TILE;           // 34816: SR (and XT) hi | lo
constexpr int OFF_W0 = 4 * S_TILE;           // 69632
constexpr int OFF_W1 = OFF_W0 + W_PAIR;      // 139264
constexpr int SMEM_TOTAL = OFF_W1 + W_PAIR;  // 208896
}

// weight images: [mat 0..8][hi|lo][n 0..127][k 0..135] bf16 (plain row-major)
// 0 Sw, 1 Uz, 2 Ug, 3 Ur, 4 Uh, 5 Wsz, 6 Wsg, 7 Wsr, 8 Wsh
__device__ __align__(16) unsigned short g_w[9][2][128][136];
// u planes (z,g,r,h), bias-folded fp32: [blk][plane][row][col]
__device__ float g_u[(size_t)NBLK * 4 * TM * HID];

// ---------- small helpers ----------
__device__ __forceinline__ uint32_t smem_u32(const void* p) {
    uint32_t a;
    asm("{ .reg .u64 t; cvta.to.shared.u64 t, %1; cvt.u32.u64 %0, t; }"
        : "=r"(a) : "l"(p));
    return a;
}
__device__ __forceinline__ float bf2f(uint32_t u) {
    return __bfloat162float(__ushort_as_bfloat16((unsigned short)u));
}
__device__ __forceinline__ uint32_t f2bf2(float lo, float hi) {
    uint32_t r;
    asm("cvt.rn.bf16x2.f32 %0, %1, %2;" : "=r"(r) : "f"(hi), "f"(lo));
    return r;
}
// write (v0,v1) split hi/lo into a 64-row tile at byte offset off
__device__ __forceinline__ void store_split(char* base, uint32_t off,
                                            float v0, float v1) {
    uint32_t hp = f2bf2(v0, v1);
    *(uint32_t*)(base + off) = hp;
    *(uint32_t*)(base + S_TILE + off) =
        f2bf2(v0 - bf2f(hp & 0xffffu), v1 - bf2f(hp >> 16));
}
// read summed hi+lo pair (cols c, c+1) from a 64-row tile
__device__ __forceinline__ float2 ld_pair(const char* base, uint32_t off) {
    uint32_t h = *(const uint32_t*)(base + off);
    uint32_t l = *(const uint32_t*)(base + S_TILE + off);
    return make_float2(bf2f(h & 0xffffu) + bf2f(l & 0xffffu),
                       bf2f(h >> 16) + bf2f(l >> 16));
}
__device__ __forceinline__ float fast_tanh(float v) {
    float e = __expf(2.0f * v);
    return 1.0f - __fdividef(2.0f, e + 1.0f);
}
__device__ __forceinline__ void ldsm4(uint32_t* r, uint32_t a) {
    asm volatile("ldmatrix.sync.aligned.m8n8.x4.shared.b16 {%0,%1,%2,%3}, [%4];"
                 : "=r"(r[0]), "=r"(r[1]), "=r"(r[2]), "=r"(r[3]) : "r"(a));
}
__device__ __forceinline__ void ldsm2(uint32_t* r, uint32_t a) {
    asm volatile("ldmatrix.sync.aligned.m8n8.x2.shared.b16 {%0,%1}, [%2];"
                 : "=r"(r[0]), "=r"(r[1]) : "r"(a));
}
__device__ __forceinline__ void mma16816(float* d, const uint32_t* a,
                                         const uint32_t* b) {
    asm volatile(
        "mma.sync.aligned.m16n8k16.row.col.f32.bf16.bf16.f32 "
        "{%0,%1,%2,%3}, {%4,%5,%6,%7}, {%8,%9}, {%0,%1,%2,%3};"
        : "+f"(d[0]), "+f"(d[1]), "+f"(d[2]), "+f"(d[3])
        : "r"(a[0]), "r"(a[1]), "r"(a[2]), "r"(a[3]), "r"(b[0]), "r"(b[1]));
}
__device__ __forceinline__ void cp_wait1() {
    asm volatile("cp.async.wait_group 1;" ::: "memory");
}
__device__ __forceinline__ void cp_wait0() {
    asm volatile("cp.async.wait_group 0;" ::: "memory");
}

// ---------- prologue: transpose + bf16-split all weight matrices ----------
__global__ void prep_weights(const float* Sw, const float* Uz, const float* Ug,
                             const float* Ur, const float* Uh, const float* Wsz,
                             const float* Wsg, const float* Wsr, const float* Wsh) {
    int m = blockIdx.x;
    const float* src;
    int Ks;
    switch (m) {
        case 0: src = Sw;  Ks = 101; break;
        case 1: src = Uz;  Ks = 101; break;
        case 2: src = Ug;  Ks = 101; break;
        case 3: src = Ur;  Ks = 101; break;
        case 4: src = Uh;  Ks = 101; break;
        case 5: src = Wsz; Ks = 128; break;
        case 6: src = Wsg; Ks = 128; break;
        case 7: src = Wsr; Ks = 128; break;
        default: src = Wsh; Ks = 128; break;
    }
    for (int idx = threadIdx.x; idx < 128 * 136; idx += blockDim.x) {
        int n = idx / 136, k = idx - n * 136;
        float v = (k < Ks) ? src[(size_t)k * HID + n] : 0.0f;  // Bt[n][k] = W[k][n]
        __nv_bfloat16 h = __float2bfloat16(v);
        g_w[m][0][n][k] = __bfloat16_as_ushort(h);
        g_w[m][1][n][k] =
            __bfloat16_as_ushort(__float2bfloat16(v - __bfloat162float(h)));
    }
}

// stage one gate (hi+lo, 69632B) into W buffer `buf`
__device__ __forceinline__ void cp_gate(uint32_t sbase, int buf, int img, int tid) {
    uint32_t sb = sbase + OFF_W0 + buf * W_PAIR;
    const char* src = (const char*)g_w[img];
#pragma unroll 1
    for (int u = tid; u < W_PAIR / 16; u += NTHR)
        asm volatile("cp.async.cg.shared.global [%0], [%1], 16;"
                     :: "r"(sb + u * 16), "l"(src + (size_t)u * 16) : "memory");
    asm volatile("cp.async.commit_group;" ::: "memory");
}

// acc[8][4] = A(16 rows @ aBase frag-layout) @ Bt(64 cols of warp) over K=16*KK.
// hi/lo split: 3 MMAs per (kk,nt). aBase points at this lane's A-hi address
// (lo at +S_TILE); wRow is this lane's B row offset within a W buffer.
template <int KK>
__device__ __forceinline__ void warp_gemm(uint32_t aBase, uint32_t wBase,
                                          float acc[8][4]) {
#pragma unroll
    for (int nt = 0; nt < 8; ++nt) {
        acc[nt][0] = 0.f; acc[nt][1] = 0.f; acc[nt][2] = 0.f; acc[nt][3] = 0.f;
    }
#pragma unroll 1
    for (int kk = 0; kk < KK; ++kk) {
        uint32_t ah[4], al[4];
        ldsm4(ah, aBase + kk * 32);
        ldsm4(al, aBase + kk * 32 + S_TILE);
#pragma unroll
        for (int nt = 0; nt < 8; ++nt) {
            uint32_t bh[2], bl[2];
            uint32_t ba = wBase + nt * (8 * LDT) + kk * 32;
            ldsm2(bh, ba);
            ldsm2(bl, ba + W_TILE);
            mma16816(acc[nt], ah, bh);
            mma16816(acc[nt], ah, bl);
            mma16816(acc[nt], al, bh);
        }
    }
}

__global__ void __launch_bounds__(NTHR, 1) dgm_mma_kernel(
    const float* __restrict__ x, const float* __restrict__ t,
    const float* __restrict__ Sw_b,
    const float* __restrict__ Uz_b, const float* __restrict__ Wsz_b,
    const float* __restrict__ Ug_b, const float* __restrict__ Wsg_b,
    const float* __restrict__ Ur_b, const float* __restrict__ Wsr_b,
    const float* __restrict__ Uh_b, const float* __restrict__ Wsh_b,
    const float* __restrict__ Wf_w, const float* __restrict__ Wf_b,
    const int* __restrict__ n_layers_p, float* __restrict__ out) {
    extern __shared__ char smem[];
    const int tid = threadIdx.x;
    const int lane = tid & 31;
    const int warp = tid >> 5;
    const int wm = warp >> 1;   // row group 0..3 (16 rows each)
    const int wn = warp & 1;    // col group 0..1 (64 cols each)
    const int row0 = blockIdx.x * TM;
    const uint32_t sbase = smem_u32(smem);

    // ldmatrix lane addresses
    const uint32_t aOffS =
        OFF_S + (wm * 16 + (lane & 15)) * LDT + ((lane >> 4) << 4);
    const uint32_t aOffSR = aOffS + (OFF_SR - OFF_S);
    const uint32_t bRow =
        (wn * 64 + (lane & 7)) * LDT + (((lane >> 3) & 1) << 4);

    // epilogue fragment coordinates
    const int erow = wm * 16 + (lane >> 2);      // rows erow, erow+8
    const int ecq = (lane & 3) * 2;              // col pair offset

    // ---- stage first gate (Sw) ----
    cp_gate(sbase, 0, 0, tid);
    int buf = 0;

    // ---- build XT tiles (hi|lo) in SR region ----
    {
        char* xh = smem + OFF_SR;
        const float4* x4 = reinterpret_cast<const float4*>(x);
        for (int idx = tid; idx < TM * 25; idx += NTHR) {
            int m = idx / 25, q = idx - m * 25;
            float4 v = x4[(size_t)(row0 + m) * 25 + q];
            float vv[4] = {v.x, v.y, v.z, v.w};
#pragma unroll
            for (int j = 0; j < 4; ++j) {
                uint32_t off = m * LDT + (q * 4 + j) * 2;
                __nv_bfloat16 h = __float2bfloat16(vv[j]);
                *(__nv_bfloat16*)(xh + off) = h;
                *(__nv_bfloat16*)(xh + S_TILE + off) =
                    __float2bfloat16(vv[j] - __bfloat162float(h));
            }
        }
        if (tid < TM) {
            float tv = t[row0 + tid];
            uint32_t off = tid * LDT + 100 * 2;
            __nv_bfloat16 h = __float2bfloat16(tv);
            *(__nv_bfloat16*)(xh + off) = h;
            *(__nv_bfloat16*)(xh + S_TILE + off) =
                __float2bfloat16(tv - __bfloat162float(h));
            for (int k = 101; k < 112; ++k) {
                uint32_t o = tid * LDT + k * 2;
                *(unsigned short*)(xh + o) = 0;
                *(unsigned short*)(xh + S_TILE + o) = 0;
            }
        }
    }

    float acc[8][4];

    // ---- S1 = tanh(xt @ SwT + Sw_b) -> S tiles ----
    cp_gate(sbase, buf ^ 1, 1, tid);  // Uz
    cp_wait1();
    __syncthreads();
    warp_gemm<7>(sbase + aOffSR, sbase + OFF_W0 + buf * W_PAIR + bRow, acc);
    __syncthreads();
#pragma unroll
    for (int nt = 0; nt < 8; ++nt) {
        int c = wn * 64 + nt * 8 + ecq;
        float2 b = __ldg((const float2*)(Sw_b + c));
        uint32_t o0 = erow * LDT + c * 2, o1 = o0 + 8 * LDT;
        store_split(smem + OFF_S, o0, fast_tanh(acc[nt][0] + b.x),
                    fast_tanh(acc[nt][1] + b.y));
        store_split(smem + OFF_S, o1, fast_tanh(acc[nt][2] + b.x),
                    fast_tanh(acc[nt][3] + b.y));
    }
    buf ^= 1;

    // ---- u planes: XT @ U*T + U*_b + Ws*_b -> g_u ----
#pragma unroll 1
    for (int pl = 0; pl < 4; ++pl) {
        int nxt = (pl < 3) ? pl + 2 : 7;  // Ug, Ur, Uh, then Wsr
        cp_gate(sbase, buf ^ 1, nxt, tid);
        cp_wait1();
        __syncthreads();
        warp_gemm<7>(sbase + aOffSR, sbase + OFF_W0 + buf * W_PAIR + bRow, acc);
        __syncthreads();
        const float *b1p, *b2p;
        if (pl == 0)      { b1p = Uz_b; b2p = Wsz_b; }
        else if (pl == 1) { b1p = Ug_b; b2p = Wsg_b; }
        else if (pl == 2) { b1p = Ur_b; b2p = Wsr_b; }
        else              { b1p = Uh_b; b2p = Wsh_b; }
        float* uP = g_u + ((size_t)blockIdx.x * 4 + pl) * TM * HID;
#pragma unroll
        for (int nt = 0; nt < 8; ++nt) {
            int c = wn * 64 + nt * 8 + ecq;
            float2 b1 = __ldg((const float2*)(b1p + c));
            float2 b2 = __ldg((const float2*)(b2p + c));
            *(float2*)(uP + erow * HID + c) =
                make_float2(acc[nt][0] + b1.x + b2.x, acc[nt][1] + b1.y + b2.y);
            *(float2*)(uP + (erow + 8) * HID + c) =
                make_float2(acc[nt][2] + b1.x + b2.x, acc[nt][3] + b1.y + b2.y);
        }
        buf ^= 1;
    }

    const int nl = *n_layers_p;
    const float* uZ = g_u + ((size_t)blockIdx.x * 4 + 0) * TM * HID;
    const float* uG = g_u + ((size_t)blockIdx.x * 4 + 1) * TM * HID;
    const float* uR = g_u + ((size_t)blockIdx.x * 4 + 2) * TM * HID;
    const float* uH = g_u + ((size_t)blockIdx.x * 4 + 3) * TM * HID;

    float h[8][4], zs[8][4];

#pragma unroll 1
    for (int l = 1; l < nl; ++l) {
        // ---- R-GEMM (Wsr staged): SR = S * tanh(uR + S@WsrT) ----
        cp_gate(sbase, buf ^ 1, 8, tid);  // Wsh
        cp_wait1();
        __syncthreads();
        warp_gemm<8>(sbase + aOffS, sbase + OFF_W0 + buf * W_PAIR + bRow, acc);
        __syncthreads();
#pragma unroll
        for (int nt = 0; nt < 8; ++nt) {
            int c = wn * 64 + nt * 8 + ecq;
            float2 u0 = *(const float2*)(uR + erow * HID + c);
            float2 u1 = *(const float2*)(uR + (erow + 8) * HID + c);
            uint32_t o0 = erow * LDT + c * 2, o1 = o0 + 8 * LDT;
            float2 s0 = ld_pair(smem + OFF_S, o0);
            float2 s1 = ld_pair(smem + OFF_S, o1);
            store_split(smem + OFF_SR, o0, s0.x * fast_tanh(acc[nt][0] + u0.x),
                        s0.y * fast_tanh(acc[nt][1] + u0.y));
            store_split(smem + OFF_SR, o1, s1.x * fast_tanh(acc[nt][2] + u1.x),
                        s1.y * fast_tanh(acc[nt][3] + u1.y));
        }
        buf ^= 1;

        // ---- H-GEMM: H = uh + SR@WshT (kept in registers) ----
        cp_gate(sbase, buf ^ 1, 5, tid);  // Wsz
        cp_wait1();
        __syncthreads();
        warp_gemm<8>(sbase + aOffSR, sbase + OFF_W0 + buf * W_PAIR + bRow, acc);
        __syncthreads();
#pragma unroll
        for (int nt = 0; nt < 8; ++nt) {
            int c = wn * 64 + nt * 8 + ecq;
            float2 u0 = *(const float2*)(uH + erow * HID + c);
            float2 u1 = *(const float2*)(uH + (erow + 8) * HID + c);
            h[nt][0] = acc[nt][0] + u0.x; h[nt][1] = acc[nt][1] + u0.y;
            h[nt][2] = acc[nt][2] + u1.x; h[nt][3] = acc[nt][3] + u1.y;
        }
        buf ^= 1;

        // ---- Z-GEMM: ZS = tanh(uZ + S@WszT) * S (registers) ----
        cp_gate(sbase, buf ^ 1, 6, tid);  // Wsg
        cp_wait1();
        __syncthreads();
        warp_gemm<8>(sbase + aOffS, sbase + OFF_W0 + buf * W_PAIR + bRow, acc);
        __syncthreads();
#pragma unroll
        for (int nt = 0; nt < 8; ++nt) {
            int c = wn * 64 + nt * 8 + ecq;
            float2 u0 = *(const float2*)(uZ + erow * HID + c);
            float2 u1 = *(const float2*)(uZ + (erow + 8) * HID + c);
            uint32_t o0 = erow * LDT + c * 2, o1 = o0 + 8 * LDT;
            float2 s0 = ld_pair(smem + OFF_S, o0);
            float2 s1 = ld_pair(smem + OFF_S, o1);
            zs[nt][0] = fast_tanh(acc[nt][0] + u0.x) * s0.x;
            zs[nt][1] = fast_tanh(acc[nt][1] + u0.y) * s0.y;
            zs[nt][2] = fast_tanh(acc[nt][2] + u1.x) * s1.x;
            zs[nt][3] = fast_tanh(acc[nt][3] + u1.y) * s1.y;
        }
        buf ^= 1;

        // ---- G-GEMM: S_new = (1 - tanh(uG + S@WsgT)) * H + ZS -> S tiles ----
        if (l + 1 < nl) { cp_gate(sbase, buf ^ 1, 7, tid); cp_wait1(); }
        else            { cp_wait0(); }
        __syncthreads();
        warp_gemm<8>(sbase + aOffS, sbase + OFF_W0 + buf * W_PAIR + bRow, acc);
        __syncthreads();  // all warps done reading S before overwriting it
#pragma unroll
        for (int nt = 0; nt < 8; ++nt) {
            int c = wn * 64 + nt * 8 + ecq;
            float2 u0 = *(const float2*)(uG + erow * HID + c);
            float2 u1 = *(const float2*)(uG + (erow + 8) * HID + c);
            uint32_t o0 = erow * LDT + c * 2, o1 = o0 + 8 * LDT;
            float g0 = fast_tanh(acc[nt][0] + u0.x);
            float g1 = fast_tanh(acc[nt][1] + u0.y);
            float g2 = fast_tanh(acc[nt][2] + u1.x);
            float g3 = fast_tanh(acc[nt][3] + u1.y);
            store_split(smem + OFF_S, o0, (1.0f - g0) * h[nt][0] + zs[nt][0],
                        (1.0f - g1) * h[nt][1] + zs[nt][1]);
            store_split(smem + OFF_S, o1, (1.0f - g2) * h[nt][2] + zs[nt][2],
                        (1.0f - g3) * h[nt][3] + zs[nt][3]);
        }
        buf ^= 1;
    }

    // ---- final: out = S @ Wf + bf (4 threads per row, shfl reduce) ----
    __syncthreads();
    {
        const int orow = tid >> 2, q = tid & 3;
        float s = 0.0f;
#pragma unroll 4
        for (int cc = 0; cc < 16; ++cc) {
            int col = q * 32 + cc * 2;
            float2 sv = ld_pair(smem + OFF_S, orow * LDT + col * 2);
            float2 wf = __ldg((const float2*)(Wf_w + col));
            s += sv.x * wf.x + sv.y * wf.y;
        }
        s += __shfl_xor_sync(0xFFFFFFFFu, s, 1);
        s += __shfl_xor_sync(0xFFFFFFFFu, s, 2);
        if (q == 0) out[row0 + orow] = s + Wf_b[0];
    }
}

extern "C" void kernel_launch(void* const* d_in, const int* in_sizes, int n_in,
                              void* d_out, int out_size) {
    const float* x     = (const float*)d_in[0];
    const float* t     = (const float*)d_in[1];
    const float* Sw_w  = (const float*)d_in[2];
    const float* Sw_b  = (const float*)d_in[3];
    const float* Uz_w  = (const float*)d_in[4];
    const float* Uz_b  = (const float*)d_in[5];
    const float* Wsz_w = (const float*)d_in[6];
    const float* Wsz_b = (const float*)d_in[7];
    const float* Ug_w  = (const float*)d_in[8];
    const float* Ug_b  = (const float*)d_in[9];
    const float* Wsg_w = (const float*)d_in[10];
    const float* Wsg_b = (const float*)d_in[11];
    const float* Ur_w  = (const float*)d_in[12];
    const float* Ur_b  = (const float*)d_in[13];
    const float* Wsr_w = (const float*)d_in[14];
    const float* Wsr_b = (const float*)d_in[15];
    const float* Uh_w  = (const float*)d_in[16];
    const float* Uh_b  = (const float*)d_in[17];
    const float* Wsh_w = (const float*)d_in[18];
    const float* Wsh_b = (const float*)d_in[19];
    const float* Wf_w  = (const float*)d_in[20];
    const float* Wf_b  = (const float*)d_in[21];
    const int*   nlp   = (const int*)d_in[22];
    float* out = (float*)d_out;

    static bool attr_set = false;
    if (!attr_set) {
        cudaFuncSetAttribute(dgm_mma_kernel,
                             cudaFuncAttributeMaxDynamicSharedMemorySize,
                             SMEM_TOTAL);
        attr_set = true;
    }
    prep_weights<<<9, 256>>>(Sw_w, Uz_w, Ug_w, Ur_w, Uh_w,
                             Wsz_w, Wsg_w, Wsr_w, Wsh_w);
    dgm_mma_kernel<<<NBLK, NTHR, SMEM_TOTAL>>>(
        x, t, Sw_b, Uz_b, Wsz_b, Ug_b, Wsg_b, Ur_b, Wsr_b, Uh_b, Wsh_b,
        Wf_w, Wf_b, nlp, out);
}

// round 13
// speedup vs baseline: 5.2123x; 1.1175x over previous
#include <cuda_runtime.h>
#include <cuda_bf16.h>
#include <cstdint>

// R13: HMMA (mma.sync.m16n8k16 bf16) fused DGM, bf16 hi/lo split.
// vs R12: (1) warp tiling 2x4 (R32,C32) cuts LDSM wavefronts 20%;
// (2) B hi+lo merged in one ldsm4 (lanes 16-31 -> lo image);
// (3) one __syncthreads per phase with deferred epilogues -> inter-warp
//     overlap of scalar epilogues with tensor MMAs; 4 syncs/layer (was 8).

namespace {
constexpr int XD   = 100;
constexpr int HID  = 128;
constexpr int TM   = 64;
constexpr int NTHR = 256;
constexpr int NBLK = 4096;          // 262144 / TM

constexpr int LDT    = 272;         // bytes per tile row (136 bf16)
constexpr int S_TILE = 64 * LDT;    // 17408
constexpr int W_TILE = 128 * LDT;   // 34816
constexpr int W_PAIR = 2 * W_TILE;  // 69632

constexpr int OFF_S  = 0;                    // S hi | lo
constexpr int OFF_SR = 2 * S_TILE;           // SR (and XT) hi | lo
constexpr int OFF_W0 = 4 * S_TILE;           // 2 W buffers
constexpr int SMEM_TOTAL = OFF_W0 + 2 * W_PAIR;  // 208896
}

// weight images: [mat][hi|lo][n][k] bf16; 0 Sw,1 Uz,2 Ug,3 Ur,4 Uh,
// 5 Wsz,6 Wsg,7 Wsr,8 Wsh
__device__ __align__(16) unsigned short g_w[9][2][128][136];
// u planes (z,g,r,h), bias-folded fp32: [blk][plane][row][col]
__device__ float g_u[(size_t)NBLK * 4 * TM * HID];

__device__ __forceinline__ uint32_t smem_u32(const void* p) {
    uint32_t a;
    asm("{ .reg .u64 t; cvta.to.shared.u64 t, %1; cvt.u32.u64 %0, t; }"
        : "=r"(a) : "l"(p));
    return a;
}
__device__ __forceinline__ float bf2f(uint32_t u) {
    return __bfloat162float(__ushort_as_bfloat16((unsigned short)u));
}
__device__ __forceinline__ uint32_t f2bf2(float lo, float hi) {
    uint32_t r;
    asm("cvt.rn.bf16x2.f32 %0, %1, %2;" : "=r"(r) : "f"(hi), "f"(lo));
    return r;
}
__device__ __forceinline__ void store_split(char* base, uint32_t off,
                                            float v0, float v1) {
    uint32_t hp = f2bf2(v0, v1);
    *(uint32_t*)(base + off) = hp;
    *(uint32_t*)(base + S_TILE + off) =
        f2bf2(v0 - bf2f(hp & 0xffffu), v1 - bf2f(hp >> 16));
}
__device__ __forceinline__ float2 ld_pair(const char* base, uint32_t off) {
    uint32_t h = *(const uint32_t*)(base + off);
    uint32_t l = *(const uint32_t*)(base + S_TILE + off);
    return make_float2(bf2f(h & 0xffffu) + bf2f(l & 0xffffu),
                       bf2f(h >> 16) + bf2f(l >> 16));
}
__device__ __forceinline__ float fast_tanh(float v) {
    float e = __expf(2.0f * v);
    return 1.0f - __fdividef(2.0f, e + 1.0f);
}
__device__ __forceinline__ void ldsm4(uint32_t* r, uint32_t a) {
    asm volatile("ldmatrix.sync.aligned.m8n8.x4.shared.b16 {%0,%1,%2,%3}, [%4];"
                 : "=r"(r[0]), "=r"(r[1]), "=r"(r[2]), "=r"(r[3]) : "r"(a));
}
__device__ __forceinline__ void mma16816(float* d, const uint32_t* a,
                                         const uint32_t* b) {
    asm volatile(
        "mma.sync.aligned.m16n8k16.row.col.f32.bf16.bf16.f32 "
        "{%0,%1,%2,%3}, {%4,%5,%6,%7}, {%8,%9}, {%0,%1,%2,%3};"
        : "+f"(d[0]), "+f"(d[1]), "+f"(d[2]), "+f"(d[3])
        : "r"(a[0]), "r"(a[1]), "r"(a[2]), "r"(a[3]), "r"(b[0]), "r"(b[1]));
}
__device__ __forceinline__ void cp_wait0() {
    asm volatile("cp.async.wait_group 0;" ::: "memory");
}

__global__ void prep_weights(const float* Sw, const float* Uz, const float* Ug,
                             const float* Ur, const float* Uh, const float* Wsz,
                             const float* Wsg, const float* Wsr, const float* Wsh) {
    int m = blockIdx.x;
    const float* src;
    int Ks;
    switch (m) {
        case 0: src = Sw;  Ks = 101; break;
        case 1: src = Uz;  Ks = 101; break;
        case 2: src = Ug;  Ks = 101; break;
        case 3: src = Ur;  Ks = 101; break;
        case 4: src = Uh;  Ks = 101; break;
        case 5: src = Wsz; Ks = 128; break;
        case 6: src = Wsg; Ks = 128; break;
        case 7: src = Wsr; Ks = 128; break;
        default: src = Wsh; Ks = 128; break;
    }
    for (int idx = threadIdx.x; idx < 128 * 136; idx += blockDim.x) {
        int n = idx / 136, k = idx - n * 136;
        float v = (k < Ks) ? src[(size_t)k * HID + n] : 0.0f;
        __nv_bfloat16 h = __float2bfloat16(v);
        g_w[m][0][n][k] = __bfloat16_as_ushort(h);
        g_w[m][1][n][k] =
            __bfloat16_as_ushort(__float2bfloat16(v - __bfloat162float(h)));
    }
}

__device__ __forceinline__ void cp_gate(uint32_t sbase, int buf, int img, int tid) {
    uint32_t sb = sbase + OFF_W0 + buf * W_PAIR;
    const char* src = (const char*)g_w[img];
#pragma unroll 1
    for (int u = tid; u < W_PAIR / 16; u += NTHR)
        asm volatile("cp.async.cg.shared.global [%0], [%1], 16;"
                     :: "r"(sb + u * 16), "l"(src + (size_t)u * 16) : "memory");
    asm volatile("cp.async.commit_group;" ::: "memory");
}

// acc[nt*2+mf][4]: warp computes m32 x n32. aHi0/aHi1 = lane addrs of the two
// m16 A-frags (hi; lo at +S_TILE). bAddr covers hi (lanes<16) and lo (>=16).
template <int KK>
__device__ __forceinline__ void warp_gemm(uint32_t aHi0, uint32_t aHi1,
                                          uint32_t bAddr, float acc[8][4]) {
#pragma unroll
    for (int i = 0; i < 8; ++i) {
        acc[i][0] = 0.f; acc[i][1] = 0.f; acc[i][2] = 0.f; acc[i][3] = 0.f;
    }
#pragma unroll
    for (int kk = 0; kk < KK; ++kk) {
        uint32_t ah0[4], ah1[4], al0[4], al1[4];
        ldsm4(ah0, aHi0 + kk * 32);
        ldsm4(al0, aHi0 + kk * 32 + S_TILE);
        ldsm4(ah1, aHi1 + kk * 32);
        ldsm4(al1, aHi1 + kk * 32 + S_TILE);
#pragma unroll
        for (int nt = 0; nt < 4; ++nt) {
            uint32_t b[4];
            ldsm4(b, bAddr + nt * (8 * LDT) + kk * 32);
            mma16816(acc[nt * 2 + 0], ah0, b);
            mma16816(acc[nt * 2 + 0], ah0, b + 2);
            mma16816(acc[nt * 2 + 0], al0, b);
            mma16816(acc[nt * 2 + 1], ah1, b);
            mma16816(acc[nt * 2 + 1], ah1, b + 2);
            mma16816(acc[nt * 2 + 1], al1, b);
        }
    }
}

__global__ void __launch_bounds__(NTHR, 1) dgm_mma_kernel(
    const float* __restrict__ x, const float* __restrict__ t,
    const float* __restrict__ Sw_b,
    const float* __restrict__ Uz_b, const float* __restrict__ Wsz_b,
    const float* __restrict__ Ug_b, const float* __restrict__ Wsg_b,
    const float* __restrict__ Ur_b, const float* __restrict__ Wsr_b,
    const float* __restrict__ Uh_b, const float* __restrict__ Wsh_b,
    const float* __restrict__ Wf_w, const float* __restrict__ Wf_b,
    const int* __restrict__ n_layers_p, float* __restrict__ out) {
    extern __shared__ char smem[];
    const int tid = threadIdx.x;
    const int lane = tid & 31;
    const int warp = tid >> 5;
    const int wm = warp >> 2;   // row group 0..1 (32 rows)
    const int wn = warp & 3;    // col group 0..3 (32 cols)
    const int row0 = blockIdx.x * TM;
    const uint32_t sbase = smem_u32(smem);

    // ldmatrix lane addresses (A m16 frags; R12-validated pattern)
    const uint32_t aS0 =
        sbase + OFF_S + (wm * 32 + (lane & 15)) * LDT + ((lane >> 4) << 4);
    const uint32_t aS1 = aS0 + 16 * LDT;
    const uint32_t aSR0 = aS0 + (OFF_SR - OFF_S);
    const uint32_t aSR1 = aSR0 + 16 * LDT;
    // B: hi for lanes 0-15 (two k-halves), lo for lanes 16-31 (same rows)
    const uint32_t bOff = (wn * 32 + (lane & 7)) * LDT +
                          (((lane >> 3) & 1) << 4) + ((lane & 16) ? W_TILE : 0);

    // epilogue fragment coordinates: rows erow + mf*16 + {0,8},
    // cols wn*32 + nt*8 + ecq + {0,1}
    const int erow = wm * 32 + (lane >> 2);
    const int ecq = (lane & 3) * 2;

    cp_gate(sbase, 0, 0, tid);  // Sw -> buf0
    int buf = 0;

    // ---- build XT tiles (hi|lo) in SR region ----
    {
        char* xh = smem + OFF_SR;
        const float4* x4 = reinterpret_cast<const float4*>(x);
        for (int idx = tid; idx < TM * 25; idx += NTHR) {
            int m = idx / 25, q = idx - m * 25;
            float4 v = x4[(size_t)(row0 + m) * 25 + q];
            float vv[4] = {v.x, v.y, v.z, v.w};
#pragma unroll
            for (int j = 0; j < 4; ++j) {
                uint32_t off = m * LDT + (q * 4 + j) * 2;
                __nv_bfloat16 h = __float2bfloat16(vv[j]);
                *(__nv_bfloat16*)(xh + off) = h;
                *(__nv_bfloat16*)(xh + S_TILE + off) =
                    __float2bfloat16(vv[j] - __bfloat162float(h));
            }
        }
        if (tid < TM) {
            float tv = t[row0 + tid];
            uint32_t off = tid * LDT + 100 * 2;
            __nv_bfloat16 h = __float2bfloat16(tv);
            *(__nv_bfloat16*)(xh + off) = h;
            *(__nv_bfloat16*)(xh + S_TILE + off) =
                __float2bfloat16(tv - __bfloat162float(h));
            for (int k = 101; k < 112; ++k) {
                uint32_t o = tid * LDT + k * 2;
                *(unsigned short*)(xh + o) = 0;
                *(unsigned short*)(xh + S_TILE + o) = 0;
            }
        }
    }

    float acc[8][4];
    const uint32_t wB0 = sbase + OFF_W0 + bOff;  // + buf*W_PAIR

    // ================= phase X0: Sw GEMM =================
    cp_wait0();
    __syncthreads();
    cp_gate(sbase, buf ^ 1, 1, tid);  // Uz
    warp_gemm<7>(aSR0, aSR1, wB0 + buf * W_PAIR, acc);
    buf ^= 1;

    // ================= phase X1: epi S1 ; Uz GEMM =================
    cp_wait0();
    __syncthreads();
    cp_gate(sbase, buf ^ 1, 2, tid);  // Ug
#pragma unroll
    for (int mf = 0; mf < 2; ++mf)
#pragma unroll
        for (int nt = 0; nt < 4; ++nt) {
            int c = wn * 32 + nt * 8 + ecq;
            float2 b = __ldg((const float2*)(Sw_b + c));
            uint32_t o0 = (erow + mf * 16) * LDT + c * 2, o1 = o0 + 8 * LDT;
            float* a = acc[nt * 2 + mf];
            store_split(smem + OFF_S, o0, fast_tanh(a[0] + b.x),
                        fast_tanh(a[1] + b.y));
            store_split(smem + OFF_S, o1, fast_tanh(a[2] + b.x),
                        fast_tanh(a[3] + b.y));
        }
    warp_gemm<7>(aSR0, aSR1, wB0 + buf * W_PAIR, acc);
    buf ^= 1;

    // ============ phases X2..X4 + first-layer handoff: u planes ============
    // epilogue of plane pl runs in the NEXT phase (deferred).
#pragma unroll 1
    for (int pl = 0; pl < 3; ++pl) {
        cp_wait0();
        __syncthreads();
        cp_gate(sbase, buf ^ 1, pl < 2 ? pl + 3 : 7, tid);  // Ur, Uh, then Wsr
        const float *b1p, *b2p;
        if (pl == 0)      { b1p = Uz_b; b2p = Wsz_b; }
        else if (pl == 1) { b1p = Ug_b; b2p = Wsg_b; }
        else              { b1p = Ur_b; b2p = Wsr_b; }
        float* uP = g_u + ((size_t)blockIdx.x * 4 + pl) * TM * HID;
#pragma unroll
        for (int mf = 0; mf < 2; ++mf)
#pragma unroll
            for (int nt = 0; nt < 4; ++nt) {
                int r = erow + mf * 16, c = wn * 32 + nt * 8 + ecq;
                float2 b1 = __ldg((const float2*)(b1p + c));
                float2 b2 = __ldg((const float2*)(b2p + c));
                float* a = acc[nt * 2 + mf];
                *(float2*)(uP + r * HID + c) =
                    make_float2(a[0] + b1.x + b2.x, a[1] + b1.y + b2.y);
                *(float2*)(uP + (r + 8) * HID + c) =
                    make_float2(a[2] + b1.x + b2.x, a[3] + b1.y + b2.y);
            }
        warp_gemm<7>(aSR0, aSR1, wB0 + buf * W_PAIR, acc);
        buf ^= 1;
    }

    const int nl = *n_layers_p;
    const float* uZ = g_u + ((size_t)blockIdx.x * 4 + 0) * TM * HID;
    const float* uG = g_u + ((size_t)blockIdx.x * 4 + 1) * TM * HID;
    const float* uR = g_u + ((size_t)blockIdx.x * 4 + 2) * TM * HID;
    const float* uH = g_u + ((size_t)blockIdx.x * 4 + 3) * TM * HID;

    float zs[8][4], G[8][4];

#pragma unroll 1
    for (int l = 1; l < nl; ++l) {
        // ---- phase R: [l==1: deferred uH epi] ; R-GEMM (Wsr in buf) ----
        cp_wait0();
        __syncthreads();
        cp_gate(sbase, buf ^ 1, 5, tid);  // Wsz
        if (l == 1) {
            float* uP = g_u + ((size_t)blockIdx.x * 4 + 3) * TM * HID;
#pragma unroll
            for (int mf = 0; mf < 2; ++mf)
#pragma unroll
                for (int nt = 0; nt < 4; ++nt) {
                    int r = erow + mf * 16, c = wn * 32 + nt * 8 + ecq;
                    float2 b1 = __ldg((const float2*)(Uh_b + c));
                    float2 b2 = __ldg((const float2*)(Wsh_b + c));
                    float* a = acc[nt * 2 + mf];
                    *(float2*)(uP + r * HID + c) =
                        make_float2(a[0] + b1.x + b2.x, a[1] + b1.y + b2.y);
                    *(float2*)(uP + (r + 8) * HID + c) =
                        make_float2(a[2] + b1.x + b2.x, a[3] + b1.y + b2.y);
                }
        }
        warp_gemm<8>(aS0, aS1, wB0 + buf * W_PAIR, acc);
        buf ^= 1;

        // ---- phase Z: epi R -> SR tiles ; Z-GEMM ----
        cp_wait0();
        __syncthreads();
        cp_gate(sbase, buf ^ 1, 6, tid);  // Wsg
#pragma unroll
        for (int mf = 0; mf < 2; ++mf)
#pragma unroll
            for (int nt = 0; nt < 4; ++nt) {
                int r = erow + mf * 16, c = wn * 32 + nt * 8 + ecq;
                float2 u0 = *(const float2*)(uR + r * HID + c);
                float2 u1 = *(const float2*)(uR + (r + 8) * HID + c);
                uint32_t o0 = r * LDT + c * 2, o1 = o0 + 8 * LDT;
                float2 s0 = ld_pair(smem + OFF_S, o0);
                float2 s1 = ld_pair(smem + OFF_S, o1);
                float* a = acc[nt * 2 + mf];
                store_split(smem + OFF_SR, o0, s0.x * fast_tanh(a[0] + u0.x),
                            s0.y * fast_tanh(a[1] + u0.y));
                store_split(smem + OFF_SR, o1, s1.x * fast_tanh(a[2] + u1.x),
                            s1.y * fast_tanh(a[3] + u1.y));
            }
        warp_gemm<8>(aS0, aS1, wB0 + buf * W_PAIR, acc);
        buf ^= 1;

        // ---- phase G: epi Z -> zs regs ; G-GEMM ----
        cp_wait0();
        __syncthreads();
        cp_gate(sbase, buf ^ 1, 8, tid);  // Wsh
#pragma unroll
        for (int mf = 0; mf < 2; ++mf)
#pragma unroll
            for (int nt = 0; nt < 4; ++nt) {
                int r = erow + mf * 16, c = wn * 32 + nt * 8 + ecq;
                float2 u0 = *(const float2*)(uZ + r * HID + c);
                float2 u1 = *(const float2*)(uZ + (r + 8) * HID + c);
                uint32_t o0 = r * LDT + c * 2, o1 = o0 + 8 * LDT;
                float2 s0 = ld_pair(smem + OFF_S, o0);
                float2 s1 = ld_pair(smem + OFF_S, o1);
                float* a = acc[nt * 2 + mf];
                float* z = zs[nt * 2 + mf];
                z[0] = fast_tanh(a[0] + u0.x) * s0.x;
                z[1] = fast_tanh(a[1] + u0.y) * s0.y;
                z[2] = fast_tanh(a[2] + u1.x) * s1.x;
                z[3] = fast_tanh(a[3] + u1.y) * s1.y;
            }
        warp_gemm<8>(aS0, aS1, wB0 + buf * W_PAIR, acc);
        buf ^= 1;

        // ---- phase H: epi G -> G regs ; H-GEMM ; epi H (immediate) ----
        cp_wait0();
        __syncthreads();
        if (l + 1 < nl) cp_gate(sbase, buf ^ 1, 7, tid);  // next Wsr
#pragma unroll
        for (int mf = 0; mf < 2; ++mf)
#pragma unroll
            for (int nt = 0; nt < 4; ++nt) {
                int r = erow + mf * 16, c = wn * 32 + nt * 8 + ecq;
                float2 u0 = *(const float2*)(uG + r * HID + c);
                float2 u1 = *(const float2*)(uG + (r + 8) * HID + c);
                float* a = acc[nt * 2 + mf];
                float* g = G[nt * 2 + mf];
                g[0] = fast_tanh(a[0] + u0.x);
                g[1] = fast_tanh(a[1] + u0.y);
                g[2] = fast_tanh(a[2] + u1.x);
                g[3] = fast_tanh(a[3] + u1.y);
            }
        warp_gemm<8>(aSR0, aSR1, wB0 + buf * W_PAIR, acc);
        buf ^= 1;
        // S_new = (1-G) * (uH + acc) + zs  -> S tiles (no S readers this phase)
#pragma unroll
        for (int mf = 0; mf < 2; ++mf)
#pragma unroll
            for (int nt = 0; nt < 4; ++nt) {
                int r = erow + mf * 16, c = wn * 32 + nt * 8 + ecq;
                float2 u0 = *(const float2*)(uH + r * HID + c);
                float2 u1 = *(const float2*)(uH + (r + 8) * HID + c);
                uint32_t o0 = r * LDT + c * 2, o1 = o0 + 8 * LDT;
                float* a = acc[nt * 2 + mf];
                float* g = G[nt * 2 + mf];
                float* z = zs[nt * 2 + mf];
                store_split(smem + OFF_S, o0,
                            (1.0f - g[0]) * (a[0] + u0.x) + z[0],
                            (1.0f - g[1]) * (a[1] + u0.y) + z[1]);
                store_split(smem + OFF_S, o1,
                            (1.0f - g[2]) * (a[2] + u1.x) + z[2],
                            (1.0f - g[3]) * (a[3] + u1.y) + z[3]);
            }
    }

    // ---- final: out = S @ Wf + bf (4 threads per row, shfl reduce) ----
    __syncthreads();
    {
        const int orow = tid >> 2, q = tid & 3;
        float s = 0.0f;
#pragma unroll 4
        for (int cc = 0; cc < 16; ++cc) {
            int col = q * 32 + cc * 2;
            float2 sv = ld_pair(smem + OFF_S, orow * LDT + col * 2);
            float2 wf = __ldg((const float2*)(Wf_w + col));
            s += sv.x * wf.x + sv.y * wf.y;
        }
        s += __shfl_xor_sync(0xFFFFFFFFu, s, 1);
        s += __shfl_xor_sync(0xFFFFFFFFu, s, 2);
        if (q == 0) out[row0 + orow] = s + Wf_b[0];
    }
}

extern "C" void kernel_launch(void* const* d_in, const int* in_sizes, int n_in,
                              void* d_out, int out_size) {
    const float* x     = (const float*)d_in[0];
    const float* t     = (const float*)d_in[1];
    const float* Sw_w  = (const float*)d_in[2];
    const float* Sw_b  = (const float*)d_in[3];
    const float* Uz_w  = (const float*)d_in[4];
    const float* Uz_b  = (const float*)d_in[5];
    const float* Wsz_w = (const float*)d_in[6];
    const float* Wsz_b = (const float*)d_in[7];
    const float* Ug_w  = (const float*)d_in[8];
    const float* Ug_b  = (const float*)d_in[9];
    const float* Wsg_w = (const float*)d_in[10];
    const float* Wsg_b = (const float*)d_in[11];
    const float* Ur_w  = (const float*)d_in[12];
    const float* Ur_b  = (const float*)d_in[13];
    const float* Wsr_w = (const float*)d_in[14];
    const float* Wsr_b = (const float*)d_in[15];
    const float* Uh_w  = (const float*)d_in[16];
    const float* Uh_b  = (const float*)d_in[17];
    const float* Wsh_w = (const float*)d_in[18];
    const float* Wsh_b = (const float*)d_in[19];
    const float* Wf_w  = (const float*)d_in[20];
    const float* Wf_b  = (const float*)d_in[21];
    const int*   nlp   = (const int*)d_in[22];
    float* out = (float*)d_out;

    static bool attr_set = false;
    if (!attr_set) {
        cudaFuncSetAttribute(dgm_mma_kernel,
                             cudaFuncAttributeMaxDynamicSharedMemorySize,
                             SMEM_TOTAL);
        attr_set = true;
    }
    prep_weights<<<9, 256>>>(Sw_w, Uz_w, Ug_w, Ur_w, Uh_w,
                             Wsz_w, Wsg_w, Wsr_w, Wsh_w);
    dgm_mma_kernel<<<NBLK, NTHR, SMEM_TOTAL>>>(
        x, t, Sw_b, Uz_b, Wsz_b, Ug_b, Wsg_b, Ur_b, Wsr_b, Uh_b, Wsh_b,
        Wf_w, Wf_b, nlp, out);
}